// round 1
// baseline (speedup 1.0000x reference)
#include <cuda_runtime.h>

// ---------------------------------------------------------------------------
// HierarchicalAttention: x -> qkv proj -> 64-token windowed attention -> proj
// B=4, N=8192, C=1024, H=16, D=64, W=64
// Round 1: full fp32 baseline (SIMT SGEMM + smem attention).
// ---------------------------------------------------------------------------

namespace {
constexpr int BATCH = 4;
constexpr int SEQ   = 8192;
constexpr int CDIM  = 1024;
constexpr int NHEAD = 16;
constexpr int HDIM  = 64;
constexpr int WIN   = 64;
constexpr int NWIN  = SEQ / WIN;          // 128
constexpr int ROWS  = BATCH * SEQ;        // 32768
}

// Scratch (allocation-free rule: __device__ globals)
__device__ float g_qkv[(size_t)BATCH * SEQ * 3 * CDIM];   // 402 MB
__device__ float g_attn[(size_t)BATCH * SEQ * CDIM];      // 134 MB

// ---------------------------------------------------------------------------
// SGEMM (NT): C[m][n] = bias[n] + sum_k A[m][k] * B[n][k]
// BM=BN=128, BK=16, 256 threads, 8x8 register tile per thread.
// M, N, K all divisible by tile sizes for this problem (asserted by launch).
// ---------------------------------------------------------------------------
__global__ __launch_bounds__(256, 2)
void sgemm_nt_bias(const float* __restrict__ A, const float* __restrict__ Bw,
                   const float* __restrict__ bias, float* __restrict__ C,
                   int M, int N, int K)
{
    __shared__ float As[16][132];   // pad 132 to break store/load conflicts
    __shared__ float Bs[16][132];

    const int t  = threadIdx.x;
    const int tx = t & 15;
    const int ty = t >> 4;
    const int m0 = blockIdx.y << 7;
    const int n0 = blockIdx.x << 7;

    float acc[8][8];
#pragma unroll
    for (int i = 0; i < 8; i++)
#pragma unroll
        for (int j = 0; j < 8; j++) acc[i][j] = 0.f;

    const int lm = t >> 2;          // 0..63 (row within tile, +64 on 2nd pass)
    const int lk = (t & 3) * 4;     // k offset (float4 granule)

    for (int kk = 0; kk < K; kk += 16) {
#pragma unroll
        for (int i = 0; i < 2; i++) {
            const int m = lm + i * 64;
            const float4 va = *(const float4*)&A [(size_t)(m0 + m) * K + kk + lk];
            const float4 vb = *(const float4*)&Bw[(size_t)(n0 + m) * K + kk + lk];
            As[lk + 0][m] = va.x; As[lk + 1][m] = va.y;
            As[lk + 2][m] = va.z; As[lk + 3][m] = va.w;
            Bs[lk + 0][m] = vb.x; Bs[lk + 1][m] = vb.y;
            Bs[lk + 2][m] = vb.z; Bs[lk + 3][m] = vb.w;
        }
        __syncthreads();
#pragma unroll
        for (int k = 0; k < 16; k++) {
            const float4 a0 = *(const float4*)&As[k][ty * 8];
            const float4 a1 = *(const float4*)&As[k][ty * 8 + 4];
            const float4 b0 = *(const float4*)&Bs[k][tx * 8];
            const float4 b1 = *(const float4*)&Bs[k][tx * 8 + 4];
            const float ar[8] = {a0.x, a0.y, a0.z, a0.w, a1.x, a1.y, a1.z, a1.w};
            const float br[8] = {b0.x, b0.y, b0.z, b0.w, b1.x, b1.y, b1.z, b1.w};
#pragma unroll
            for (int i = 0; i < 8; i++)
#pragma unroll
                for (int j = 0; j < 8; j++)
                    acc[i][j] = fmaf(ar[i], br[j], acc[i][j]);
        }
        __syncthreads();
    }

    const float4 bb0 = *(const float4*)&bias[n0 + tx * 8];
    const float4 bb1 = *(const float4*)&bias[n0 + tx * 8 + 4];
#pragma unroll
    for (int i = 0; i < 8; i++) {
        const int m = m0 + ty * 8 + i;
        float4 r0, r1;
        r0.x = acc[i][0] + bb0.x; r0.y = acc[i][1] + bb0.y;
        r0.z = acc[i][2] + bb0.z; r0.w = acc[i][3] + bb0.w;
        r1.x = acc[i][4] + bb1.x; r1.y = acc[i][5] + bb1.y;
        r1.z = acc[i][6] + bb1.z; r1.w = acc[i][7] + bb1.w;
        float4* cp = (float4*)&C[(size_t)m * N + n0 + tx * 8];
        cp[0] = r0;
        cp[1] = r1;
    }
}

// ---------------------------------------------------------------------------
// Windowed attention: one CTA per (window, head, batch).
// qkv layout: [B, N, 3*C], inner index = s*1024 + h*64 + d  (s in {q,k,v})
// out layout: [B, N, C],   inner index = h*64 + d
// 256 threads; thread (qg = t/16, kg = t%16) owns a 4x4 tile with
// interleaved rows/cols (q = qg+16i, k/d = kg+16j) -> conflict-free LDS.
// ---------------------------------------------------------------------------
__global__ __launch_bounds__(256)
void win_attn_kernel(const float* __restrict__ qkv, float* __restrict__ out)
{
    extern __shared__ float sm[];
    float* Qs = sm;                 // [64][65]
    float* Ks = Qs + 64 * 65;
    float* Vs = Ks + 64 * 65;
    float* Ps = Vs + 64 * 65;

    const int t = threadIdx.x;
    const int w = blockIdx.x, h = blockIdx.y, b = blockIdx.z;
    const int n0 = w * WIN;
    const size_t base = ((size_t)b * SEQ + n0) * (3 * CDIM) + (size_t)h * HDIM;

    // Load Q, K, V tiles (64x64 each), float4 global reads, scalar smem stores
#pragma unroll
    for (int i = 0; i < 4; i++) {
        const int e   = t + i * 256;          // 0..1023
        const int row = e >> 4;
        const int dc  = (e & 15) * 4;
        const float* src = qkv + base + (size_t)row * (3 * CDIM) + dc;
        const float4 q4 = *(const float4*)(src);
        const float4 k4 = *(const float4*)(src + CDIM);
        const float4 v4 = *(const float4*)(src + 2 * CDIM);
        const int o = row * 65 + dc;
        Qs[o] = q4.x; Qs[o + 1] = q4.y; Qs[o + 2] = q4.z; Qs[o + 3] = q4.w;
        Ks[o] = k4.x; Ks[o + 1] = k4.y; Ks[o + 2] = k4.z; Ks[o + 3] = k4.w;
        Vs[o] = v4.x; Vs[o + 1] = v4.y; Vs[o + 2] = v4.z; Vs[o + 3] = v4.w;
    }
    __syncthreads();

    const int qg = t >> 4;   // 0..15
    const int kg = t & 15;   // 0..15

    // S = Q K^T * scale  (4x4 per thread, interleaved)
    float s[4][4];
#pragma unroll
    for (int i = 0; i < 4; i++)
#pragma unroll
        for (int j = 0; j < 4; j++) s[i][j] = 0.f;

#pragma unroll 8
    for (int d = 0; d < 64; d++) {
        float qr[4], kr[4];
#pragma unroll
        for (int i = 0; i < 4; i++) qr[i] = Qs[(qg + 16 * i) * 65 + d];
#pragma unroll
        for (int j = 0; j < 4; j++) kr[j] = Ks[(kg + 16 * j) * 65 + d];
#pragma unroll
        for (int i = 0; i < 4; i++)
#pragma unroll
            for (int j = 0; j < 4; j++)
                s[i][j] = fmaf(qr[i], kr[j], s[i][j]);
    }

    // Row softmax (row q = qg+16i is owned by the 16 lanes sharing qg)
    float inv[4];
#pragma unroll
    for (int i = 0; i < 4; i++) {
        float mx = -3.4e38f;
#pragma unroll
        for (int j = 0; j < 4; j++) {
            s[i][j] *= 0.125f;                      // 1/sqrt(64)
            mx = fmaxf(mx, s[i][j]);
        }
        mx = fmaxf(mx, __shfl_xor_sync(0xffffffffu, mx, 1));
        mx = fmaxf(mx, __shfl_xor_sync(0xffffffffu, mx, 2));
        mx = fmaxf(mx, __shfl_xor_sync(0xffffffffu, mx, 4));
        mx = fmaxf(mx, __shfl_xor_sync(0xffffffffu, mx, 8));
        float sum = 0.f;
#pragma unroll
        for (int j = 0; j < 4; j++) {
            s[i][j] = __expf(s[i][j] - mx);
            sum += s[i][j];
        }
        sum += __shfl_xor_sync(0xffffffffu, sum, 1);
        sum += __shfl_xor_sync(0xffffffffu, sum, 2);
        sum += __shfl_xor_sync(0xffffffffu, sum, 4);
        sum += __shfl_xor_sync(0xffffffffu, sum, 8);
        inv[i] = 1.f / sum;
#pragma unroll
        for (int j = 0; j < 4; j++)
            Ps[(qg + 16 * i) * 65 + kg + 16 * j] = s[i][j];
    }
    __syncwarp();   // each row's producers/consumers are in the same warp

    // O = P V  (unnormalized P; scale by inv at the end)
    float o[4][4];
#pragma unroll
    for (int i = 0; i < 4; i++)
#pragma unroll
        for (int j = 0; j < 4; j++) o[i][j] = 0.f;

#pragma unroll 8
    for (int k = 0; k < 64; k++) {
        float pr[4], vr[4];
#pragma unroll
        for (int i = 0; i < 4; i++) pr[i] = Ps[(qg + 16 * i) * 65 + k];
#pragma unroll
        for (int j = 0; j < 4; j++) vr[j] = Vs[k * 65 + kg + 16 * j];
#pragma unroll
        for (int i = 0; i < 4; i++)
#pragma unroll
            for (int j = 0; j < 4; j++)
                o[i][j] = fmaf(pr[i], vr[j], o[i][j]);
    }

#pragma unroll
    for (int i = 0; i < 4; i++) {
        const size_t orow = ((size_t)b * SEQ + n0 + qg + 16 * i) * CDIM
                          + (size_t)h * HDIM + kg;
#pragma unroll
        for (int j = 0; j < 4; j++)
            out[orow + 16 * j] = o[i][j] * inv[i];
    }
}

// ---------------------------------------------------------------------------
// kernel_launch: 3 sequential launches on the default (capture) stream.
// ---------------------------------------------------------------------------
extern "C" void kernel_launch(void* const* d_in, const int* in_sizes, int n_in,
                              void* d_out, int out_size)
{
    const float* x      = (const float*)d_in[0];
    const float* w_qkv  = (const float*)d_in[1];
    const float* b_qkv  = (const float*)d_in[2];
    const float* w_proj = (const float*)d_in[3];
    const float* b_proj = (const float*)d_in[4];
    float* out = (float*)d_out;

    float *qkv_ptr = nullptr, *attn_ptr = nullptr;
    cudaGetSymbolAddress((void**)&qkv_ptr, g_qkv);
    cudaGetSymbolAddress((void**)&attn_ptr, g_attn);

    const int attn_smem = 4 * 64 * 65 * (int)sizeof(float);   // 66,560 B
    cudaFuncSetAttribute(win_attn_kernel,
                         cudaFuncAttributeMaxDynamicSharedMemorySize, attn_smem);

    const dim3 blk(256);

    // 1) QKV projection: [32768,1024] @ [3072,1024]^T + b -> g_qkv
    sgemm_nt_bias<<<dim3(3 * CDIM / 128, ROWS / 128), blk>>>(
        x, w_qkv, b_qkv, qkv_ptr, ROWS, 3 * CDIM, CDIM);

    // 2) Windowed attention -> g_attn ([B,N,C] layout)
    win_attn_kernel<<<dim3(NWIN, NHEAD, BATCH), blk, attn_smem>>>(qkv_ptr, attn_ptr);

    // 3) Output projection: [32768,1024] @ [1024,1024]^T + b -> out
    sgemm_nt_bias<<<dim3(CDIM / 128, ROWS / 128), blk>>>(
        attn_ptr, w_proj, b_proj, out, ROWS, CDIM, CDIM);
}

// round 5
// speedup vs baseline: 1.8125x; 1.8125x over previous
#include <cuda_runtime.h>
#include <cstdint>

// ---------------------------------------------------------------------------
// HierarchicalAttention on GB300 (sm_103a)
// Round 5: legacy mma.sync tf32 GEMMs (tcgen05 unavailable: harness compiles
// through virtual compute_103). Weight hi/lo tf32 split for accuracy.
// B=4, N=8192, C=1024, H=16, D=64, W=64
// ---------------------------------------------------------------------------

namespace {
constexpr int BATCH = 4;
constexpr int SEQ   = 8192;
constexpr int CDIM  = 1024;
constexpr int NHEAD = 16;
constexpr int HDIM  = 64;
constexpr int WIN   = 64;
constexpr int NWIN  = SEQ / WIN;          // 128
constexpr int ROWS  = BATCH * SEQ;        // 32768

constexpr int TILE_BYTES  = 128 * 32 * 4;             // 16 KB (128 rows x 32 floats)
constexpr int STAGE_BYTES = 3 * TILE_BYTES;           // A + Bhi + Blo = 48 KB
constexpr int NSTAGE      = 4;
constexpr int GEMM_SMEM   = NSTAGE * STAGE_BYTES;     // 196,608 B
}

// Scratch (__device__ globals per allocation rules)
__device__ float g_x    [(size_t)ROWS * CDIM];          // rn-tf32-rounded x
__device__ float g_qkv  [(size_t)ROWS * 3 * CDIM];
__device__ float g_attn [(size_t)ROWS * CDIM];          // rn-tf32-rounded attn out
__device__ float g_wqkv_hi[(size_t)3 * CDIM * CDIM];
__device__ float g_wqkv_lo[(size_t)3 * CDIM * CDIM];
__device__ float g_wproj_hi[(size_t)CDIM * CDIM];
__device__ float g_wproj_lo[(size_t)CDIM * CDIM];

// ---------------------------------------------------------------------------
// Helpers
// ---------------------------------------------------------------------------
#define SWZ128(x) ((x) ^ (((x) >> 3) & 0x70))

__device__ __forceinline__ void cp_async16(void* dst, const void* src) {
    uint32_t d;
    asm("{ .reg .u64 t; cvta.to.shared.u64 t, %1; cvt.u32.u64 %0, t; }"
        : "=r"(d) : "l"(dst));
    asm volatile("cp.async.cg.shared.global [%0], [%1], 16;" :: "r"(d), "l"(src));
}

__device__ __forceinline__ float rn_tf32(float v) {
    uint32_t u;
    asm("cvt.rna.tf32.f32 %0, %1;" : "=r"(u) : "f"(v));
    return __uint_as_float(u);
}

// mma.sync m16n8k8 tf32: D += A * B   (A row-major 16x8, B col-major 8x8)
__device__ __forceinline__ void mma_tf32(float* c, const uint32_t* a, const uint32_t* b) {
    asm volatile(
        "mma.sync.aligned.m16n8k8.row.col.f32.tf32.tf32.f32 "
        "{%0,%1,%2,%3}, {%4,%5,%6,%7}, {%8,%9}, {%0,%1,%2,%3};"
        : "+f"(c[0]), "+f"(c[1]), "+f"(c[2]), "+f"(c[3])
        : "r"(a[0]), "r"(a[1]), "r"(a[2]), "r"(a[3]), "r"(b[0]), "r"(b[1]));
}

// ---------------------------------------------------------------------------
// Conversion kernels
// ---------------------------------------------------------------------------
__global__ void round_x_tf32(const float* __restrict__ in, float* __restrict__ outp, int n4) {
    int i = blockIdx.x * blockDim.x + threadIdx.x;
    if (i < n4) {
        float4 v = ((const float4*)in)[i];
        v.x = rn_tf32(v.x); v.y = rn_tf32(v.y);
        v.z = rn_tf32(v.z); v.w = rn_tf32(v.w);
        ((float4*)outp)[i] = v;
    }
}

__global__ void split_w_tf32(const float* __restrict__ w, float* __restrict__ hi,
                             float* __restrict__ lo, int n) {
    int i = blockIdx.x * blockDim.x + threadIdx.x;
    if (i < n) {
        float v = w[i];
        float h = rn_tf32(v);
        hi[i] = h;
        lo[i] = rn_tf32(v - h);
    }
}

// ---------------------------------------------------------------------------
// tf32 GEMM (mma.sync): C[m][n] = bias[n] + sum_k A[m][k]*(Bhi[n][k]+Blo[n][k])
// Tile 128x128, BK=32 floats, 4-stage cp.async, 8 warps (2x4), 64x32/warp.
// ---------------------------------------------------------------------------
__device__ __forceinline__ void load_tile_part(char* sbase, const float* __restrict__ g,
                                               int ld, int row0, int kk, int tid) {
#pragma unroll
    for (int i = 0; i < 2; i++) {
        const int e = tid + i * 256;       // 0..511
        const int r = e >> 2;              // row 0..127
        const int c = e & 3;               // 16B granule 0..7 (BK=32 floats=128B: 8 granules)
        // each thread covers 2 granules: c and c+4
#pragma unroll
        for (int h = 0; h < 2; h++) {
            const int gr = c + h * 4;
            cp_async16(sbase + SWZ128(r * 128 + gr * 16),
                       g + (size_t)(row0 + r) * ld + kk + gr * 4);
        }
    }
}

__global__ __launch_bounds__(256, 1)
void gemm_tf32_split(const float* __restrict__ A, const float* __restrict__ Bhi,
                     const float* __restrict__ Blo, const float* __restrict__ bias,
                     float* __restrict__ C, int K, int Ntot)
{
    extern __shared__ __align__(16) char smem[];
    const int tid  = threadIdx.x;
    const int wid  = tid >> 5;
    const int lane = tid & 31;
    const int m0 = blockIdx.y << 7;
    const int n0 = blockIdx.x << 7;
    const int nch = K >> 5;                          // 32

    const int wm = (wid & 1) * 64;                   // warp m offset in tile
    const int wn = (wid >> 1) * 32;                  // warp n offset in tile
    const int rq = lane >> 2;                        // 0..7
    const int cq = lane & 3;                         // 0..3

    // Precompute swizzled fragment base byte-offsets (kstep/half folded by XOR)
    int swzA[4], swzB[4];
#pragma unroll
    for (int mt = 0; mt < 4; mt++)
        swzA[mt] = SWZ128((wm + mt * 16 + rq) * 128 + cq * 4);
#pragma unroll
    for (int nt = 0; nt < 4; nt++)
        swzB[nt] = SWZ128((wn + nt * 8 + rq) * 128 + cq * 4);

    float acc[4][4][4];
#pragma unroll
    for (int mt = 0; mt < 4; mt++)
#pragma unroll
        for (int nt = 0; nt < 4; nt++)
#pragma unroll
            for (int i = 0; i < 4; i++) acc[mt][nt][i] = 0.f;

    // Prologue: chunks 0..2
#pragma unroll
    for (int j = 0; j < 3; j++) {
        char* st = smem + j * STAGE_BYTES;
        load_tile_part(st,                  A,   K, m0, j * 32, tid);
        load_tile_part(st + TILE_BYTES,     Bhi, K, n0, j * 32, tid);
        load_tile_part(st + 2 * TILE_BYTES, Blo, K, n0, j * 32, tid);
        asm volatile("cp.async.commit_group;");
    }

    for (int k = 0; k < nch; k++) {
        asm volatile("cp.async.wait_group 2;");      // chunk k resident
        __syncthreads();

        const char* st = smem + (k & 3) * STAGE_BYTES;
        const char* sA = st;
        const char* sH = st + TILE_BYTES;
        const char* sL = st + 2 * TILE_BYTES;

#pragma unroll
        for (int ks = 0; ks < 4; ks++) {
            const int ko = ks << 5;                  // kstep byte XOR (8 floats = 32 B)
            uint32_t af[4][4];
#pragma unroll
            for (int mt = 0; mt < 4; mt++) {
                const int a0 = swzA[mt] ^ ko;
                af[mt][0] = *(const uint32_t*)(sA + a0);
                af[mt][1] = *(const uint32_t*)(sA + a0 + 1024);        // row+8
                af[mt][2] = *(const uint32_t*)(sA + (a0 ^ 16));        // k+4
                af[mt][3] = *(const uint32_t*)(sA + ((a0 + 1024) ^ 16));
            }
#pragma unroll
            for (int nt = 0; nt < 4; nt++) {
                const int b0 = swzB[nt] ^ ko;
                uint32_t bh[2], bl[2];
                bh[0] = *(const uint32_t*)(sH + b0);
                bh[1] = *(const uint32_t*)(sH + (b0 ^ 16));
                bl[0] = *(const uint32_t*)(sL + b0);
                bl[1] = *(const uint32_t*)(sL + (b0 ^ 16));
#pragma unroll
                for (int mt = 0; mt < 4; mt++) {
                    mma_tf32(acc[mt][nt], af[mt], bh);
                    mma_tf32(acc[mt][nt], af[mt], bl);
                }
            }
        }
        __syncthreads();                             // protect stage before refill

        const int j = k + 3;
        if (j < nch) {
            char* ld = smem + (j & 3) * STAGE_BYTES;
            load_tile_part(ld,                  A,   K, m0, j * 32, tid);
            load_tile_part(ld + TILE_BYTES,     Bhi, K, n0, j * 32, tid);
            load_tile_part(ld + 2 * TILE_BYTES, Blo, K, n0, j * 32, tid);
        }
        asm volatile("cp.async.commit_group;");      // (possibly empty) keep ledger
    }

    // Epilogue: direct STG with bias (fragment layout: c0/c1 row, c2/c3 row+8)
#pragma unroll
    for (int nt = 0; nt < 4; nt++) {
        const int col = n0 + wn + nt * 8 + cq * 2;
        const float2 b2 = *(const float2*)&bias[col];
#pragma unroll
        for (int mt = 0; mt < 4; mt++) {
            const int row = m0 + wm + mt * 16 + rq;
            float2 v0, v1;
            v0.x = acc[mt][nt][0] + b2.x; v0.y = acc[mt][nt][1] + b2.y;
            v1.x = acc[mt][nt][2] + b2.x; v1.y = acc[mt][nt][3] + b2.y;
            *(float2*)&C[(size_t)row * Ntot + col]       = v0;
            *(float2*)&C[(size_t)(row + 8) * Ntot + col] = v1;
        }
    }
}

// ---------------------------------------------------------------------------
// Windowed attention (fp32), one CTA per (window, head, batch).
// Output rn-rounded to tf32 (feeds the second GEMM's A operand).
// ---------------------------------------------------------------------------
__global__ __launch_bounds__(256)
void win_attn_kernel(const float* __restrict__ qkv, float* __restrict__ out)
{
    extern __shared__ float sm[];
    float* Qs = sm;                 // [64][65]
    float* Ks = Qs + 64 * 65;
    float* Vs = Ks + 64 * 65;
    float* Ps = Vs + 64 * 65;

    const int t = threadIdx.x;
    const int w = blockIdx.x, h = blockIdx.y, b = blockIdx.z;
    const int n0 = w * WIN;
    const size_t base = ((size_t)b * SEQ + n0) * (3 * CDIM) + (size_t)h * HDIM;

#pragma unroll
    for (int i = 0; i < 4; i++) {
        const int e   = t + i * 256;
        const int row = e >> 4;
        const int dc  = (e & 15) * 4;
        const float* src = qkv + base + (size_t)row * (3 * CDIM) + dc;
        const float4 q4 = *(const float4*)(src);
        const float4 k4 = *(const float4*)(src + CDIM);
        const float4 v4 = *(const float4*)(src + 2 * CDIM);
        const int o = row * 65 + dc;
        Qs[o] = q4.x; Qs[o + 1] = q4.y; Qs[o + 2] = q4.z; Qs[o + 3] = q4.w;
        Ks[o] = k4.x; Ks[o + 1] = k4.y; Ks[o + 2] = k4.z; Ks[o + 3] = k4.w;
        Vs[o] = v4.x; Vs[o + 1] = v4.y; Vs[o + 2] = v4.z; Vs[o + 3] = v4.w;
    }
    __syncthreads();

    const int qg = t >> 4;
    const int kg = t & 15;

    float s[4][4];
#pragma unroll
    for (int i = 0; i < 4; i++)
#pragma unroll
        for (int j = 0; j < 4; j++) s[i][j] = 0.f;

#pragma unroll 8
    for (int d = 0; d < 64; d++) {
        float qr[4], kr[4];
#pragma unroll
        for (int i = 0; i < 4; i++) qr[i] = Qs[(qg + 16 * i) * 65 + d];
#pragma unroll
        for (int j = 0; j < 4; j++) kr[j] = Ks[(kg + 16 * j) * 65 + d];
#pragma unroll
        for (int i = 0; i < 4; i++)
#pragma unroll
            for (int j = 0; j < 4; j++)
                s[i][j] = fmaf(qr[i], kr[j], s[i][j]);
    }

    float inv[4];
#pragma unroll
    for (int i = 0; i < 4; i++) {
        float mx = -3.4e38f;
#pragma unroll
        for (int j = 0; j < 4; j++) {
            s[i][j] *= 0.125f;
            mx = fmaxf(mx, s[i][j]);
        }
        mx = fmaxf(mx, __shfl_xor_sync(0xffffffffu, mx, 1));
        mx = fmaxf(mx, __shfl_xor_sync(0xffffffffu, mx, 2));
        mx = fmaxf(mx, __shfl_xor_sync(0xffffffffu, mx, 4));
        mx = fmaxf(mx, __shfl_xor_sync(0xffffffffu, mx, 8));
        float sum = 0.f;
#pragma unroll
        for (int j = 0; j < 4; j++) {
            s[i][j] = __expf(s[i][j] - mx);
            sum += s[i][j];
        }
        sum += __shfl_xor_sync(0xffffffffu, sum, 1);
        sum += __shfl_xor_sync(0xffffffffu, sum, 2);
        sum += __shfl_xor_sync(0xffffffffu, sum, 4);
        sum += __shfl_xor_sync(0xffffffffu, sum, 8);
        inv[i] = 1.f / sum;
#pragma unroll
        for (int j = 0; j < 4; j++)
            Ps[(qg + 16 * i) * 65 + kg + 16 * j] = s[i][j];
    }
    __syncwarp();

    float o[4][4];
#pragma unroll
    for (int i = 0; i < 4; i++)
#pragma unroll
        for (int j = 0; j < 4; j++) o[i][j] = 0.f;

#pragma unroll 8
    for (int k = 0; k < 64; k++) {
        float pr[4], vr[4];
#pragma unroll
        for (int i = 0; i < 4; i++) pr[i] = Ps[(qg + 16 * i) * 65 + k];
#pragma unroll
        for (int j = 0; j < 4; j++) vr[j] = Vs[k * 65 + kg + 16 * j];
#pragma unroll
        for (int i = 0; i < 4; i++)
#pragma unroll
            for (int j = 0; j < 4; j++)
                o[i][j] = fmaf(pr[i], vr[j], o[i][j]);
    }

#pragma unroll
    for (int i = 0; i < 4; i++) {
        const size_t orow = ((size_t)b * SEQ + n0 + qg + 16 * i) * CDIM
                          + (size_t)h * HDIM + kg;
#pragma unroll
        for (int j = 0; j < 4; j++)
            out[orow + 16 * j] = rn_tf32(o[i][j] * inv[i]);
    }
}

// ---------------------------------------------------------------------------
// kernel_launch
// ---------------------------------------------------------------------------
extern "C" void kernel_launch(void* const* d_in, const int* in_sizes, int n_in,
                              void* d_out, int out_size)
{
    const float* x      = (const float*)d_in[0];
    const float* w_qkv  = (const float*)d_in[1];
    const float* b_qkv  = (const float*)d_in[2];
    const float* w_proj = (const float*)d_in[3];
    const float* b_proj = (const float*)d_in[4];
    float* out = (float*)d_out;

    float *xr, *qkv, *attn, *wq_hi, *wq_lo, *wp_hi, *wp_lo;
    cudaGetSymbolAddress((void**)&xr,    g_x);
    cudaGetSymbolAddress((void**)&qkv,   g_qkv);
    cudaGetSymbolAddress((void**)&attn,  g_attn);
    cudaGetSymbolAddress((void**)&wq_hi, g_wqkv_hi);
    cudaGetSymbolAddress((void**)&wq_lo, g_wqkv_lo);
    cudaGetSymbolAddress((void**)&wp_hi, g_wproj_hi);
    cudaGetSymbolAddress((void**)&wp_lo, g_wproj_lo);

    cudaFuncSetAttribute(gemm_tf32_split,
                         cudaFuncAttributeMaxDynamicSharedMemorySize, GEMM_SMEM);
    const int attn_smem = 4 * 64 * 65 * (int)sizeof(float);
    cudaFuncSetAttribute(win_attn_kernel,
                         cudaFuncAttributeMaxDynamicSharedMemorySize, attn_smem);

    // Pre-passes: rn-round x, split weights into tf32 hi/lo
    const int nwq = 3 * CDIM * CDIM, nwp = CDIM * CDIM;
    split_w_tf32<<<(nwq + 255) / 256, 256>>>(w_qkv, wq_hi, wq_lo, nwq);
    split_w_tf32<<<(nwp + 255) / 256, 256>>>(w_proj, wp_hi, wp_lo, nwp);
    const int n4 = ROWS * CDIM / 4;
    round_x_tf32<<<(n4 + 255) / 256, 256>>>(x, xr, n4);

    // 1) QKV projection (tensor cores, mma.sync tf32)
    gemm_tf32_split<<<dim3(3 * CDIM / 128, ROWS / 128), 256, GEMM_SMEM>>>(
        xr, wq_hi, wq_lo, b_qkv, qkv, CDIM, 3 * CDIM);

    // 2) Windowed attention (fp32, tf32-rounded output)
    win_attn_kernel<<<dim3(NWIN, NHEAD, BATCH), 256, attn_smem>>>(qkv, attn);

    // 3) Output projection (tensor cores, mma.sync tf32)
    gemm_tf32_split<<<dim3(CDIM / 128, ROWS / 128), 256, GEMM_SMEM>>>(
        attn, wp_hi, wp_lo, b_proj, out, CDIM, CDIM);
}

// round 7
// speedup vs baseline: 2.7829x; 1.5354x over previous
#include <cuda_runtime.h>
#include <cstdint>

// ---------------------------------------------------------------------------
// HierarchicalAttention on GB300 (sm_103a)
// Round 7 (= round 6 resubmit after infra timeout):
// single-pass tf32 mma.sync GEMMs (rna-rounded operands), 16 warps,
// 5-stage cp.async pipeline. fp32 windowed attention.
// B=4, N=8192, C=1024, H=16, D=64, W=64
// ---------------------------------------------------------------------------

namespace {
constexpr int BATCH = 4;
constexpr int SEQ   = 8192;
constexpr int CDIM  = 1024;
constexpr int NHEAD = 16;
constexpr int HDIM  = 64;
constexpr int WIN   = 64;
constexpr int NWIN  = SEQ / WIN;          // 128
constexpr int ROWS  = BATCH * SEQ;        // 32768

constexpr int TILE_BYTES  = 128 * 32 * 4;             // 16 KB (128 rows x 32 floats)
constexpr int STAGE_BYTES = 2 * TILE_BYTES;           // A + B = 32 KB
constexpr int NSTAGE      = 5;
constexpr int GEMM_SMEM   = NSTAGE * STAGE_BYTES;     // 163,840 B
}

// Scratch (__device__ globals per allocation rules)
__device__ float g_x    [(size_t)ROWS * CDIM];          // rna-tf32-rounded x
__device__ float g_qkv  [(size_t)ROWS * 3 * CDIM];
__device__ float g_attn [(size_t)ROWS * CDIM];          // rna-tf32-rounded attn out
__device__ float g_wqkv_r [(size_t)3 * CDIM * CDIM];    // rna-tf32-rounded weights
__device__ float g_wproj_r[(size_t)CDIM * CDIM];

// ---------------------------------------------------------------------------
// Helpers
// ---------------------------------------------------------------------------
#define SWZ128(x) ((x) ^ (((x) >> 3) & 0x70))

__device__ __forceinline__ void cp_async16(void* dst, const void* src) {
    uint32_t d;
    asm("{ .reg .u64 t; cvta.to.shared.u64 t, %1; cvt.u32.u64 %0, t; }"
        : "=r"(d) : "l"(dst));
    asm volatile("cp.async.cg.shared.global [%0], [%1], 16;" :: "r"(d), "l"(src));
}

__device__ __forceinline__ float rn_tf32(float v) {
    uint32_t u;
    asm("cvt.rna.tf32.f32 %0, %1;" : "=r"(u) : "f"(v));
    return __uint_as_float(u);
}

// mma.sync m16n8k8 tf32: D += A * B   (A row-major 16x8, B col-major 8x8)
__device__ __forceinline__ void mma_tf32(float* c, const uint32_t* a, const uint32_t* b) {
    asm volatile(
        "mma.sync.aligned.m16n8k8.row.col.f32.tf32.tf32.f32 "
        "{%0,%1,%2,%3}, {%4,%5,%6,%7}, {%8,%9}, {%0,%1,%2,%3};"
        : "+f"(c[0]), "+f"(c[1]), "+f"(c[2]), "+f"(c[3])
        : "r"(a[0]), "r"(a[1]), "r"(a[2]), "r"(a[3]), "r"(b[0]), "r"(b[1]));
}

// ---------------------------------------------------------------------------
// Conversion kernels (rna-round to tf32 grid; kills truncation bias in mma)
// ---------------------------------------------------------------------------
__global__ void round_tf32_vec(const float* __restrict__ in, float* __restrict__ outp, int n4) {
    int i = blockIdx.x * blockDim.x + threadIdx.x;
    if (i < n4) {
        float4 v = ((const float4*)in)[i];
        v.x = rn_tf32(v.x); v.y = rn_tf32(v.y);
        v.z = rn_tf32(v.z); v.w = rn_tf32(v.w);
        ((float4*)outp)[i] = v;
    }
}

// ---------------------------------------------------------------------------
// tf32 GEMM (mma.sync): C[m][n] = bias[n] + sum_k A[m][k] * B[n][k]
// Tile 128x128, BK=32 floats, 5-stage cp.async, 16 warps (4x4), 32x32/warp.
// ---------------------------------------------------------------------------
__device__ __forceinline__ void load_tile_part(char* sbase, const float* __restrict__ g,
                                               int ld, int row0, int kk, int tid) {
#pragma unroll
    for (int i = 0; i < 2; i++) {
        const int e = tid + i * 512;       // 0..1023
        const int r = e >> 3;              // row 0..127
        const int c = e & 7;               // 16B granule 0..7
        cp_async16(sbase + SWZ128(r * 128 + c * 16),
                   g + (size_t)(row0 + r) * ld + kk + c * 4);
    }
}

__global__ __launch_bounds__(512, 1)
void gemm_tf32(const float* __restrict__ A, const float* __restrict__ B,
               const float* __restrict__ bias, float* __restrict__ C,
               int K, int Ntot)
{
    extern __shared__ __align__(16) char smem[];
    const int tid  = threadIdx.x;
    const int wid  = tid >> 5;
    const int lane = tid & 31;
    const int m0 = blockIdx.y << 7;
    const int n0 = blockIdx.x << 7;
    const int nch = K >> 5;                          // 32

    const int wm = (wid & 3) * 32;                   // warp m offset in tile
    const int wn = (wid >> 2) * 32;                  // warp n offset in tile
    const int rq = lane >> 2;                        // 0..7
    const int cq = lane & 3;                         // 0..3

    // Swizzled fragment base byte-offsets (kstep/half folded by XOR)
    int swzA[2], swzB[4];
#pragma unroll
    for (int mt = 0; mt < 2; mt++)
        swzA[mt] = SWZ128((wm + mt * 16 + rq) * 128 + cq * 4);
#pragma unroll
    for (int nt = 0; nt < 4; nt++)
        swzB[nt] = SWZ128((wn + nt * 8 + rq) * 128 + cq * 4);

    float acc[2][4][4];
#pragma unroll
    for (int mt = 0; mt < 2; mt++)
#pragma unroll
        for (int nt = 0; nt < 4; nt++)
#pragma unroll
            for (int i = 0; i < 4; i++) acc[mt][nt][i] = 0.f;

    // Prologue: chunks 0..3 -> stages 0..3
#pragma unroll
    for (int j = 0; j < 4; j++) {
        char* st = smem + j * STAGE_BYTES;
        load_tile_part(st,              A, K, m0, j * 32, tid);
        load_tile_part(st + TILE_BYTES, B, K, n0, j * 32, tid);
        asm volatile("cp.async.commit_group;");
    }

    int cur = 0, nxt = 4;                            // stage indices mod 5
    for (int k = 0; k < nch; k++) {
        asm volatile("cp.async.wait_group 3;");      // chunk k resident
        __syncthreads();

        const char* sA = smem + cur * STAGE_BYTES;
        const char* sB = sA + TILE_BYTES;

#pragma unroll
        for (int ks = 0; ks < 4; ks++) {
            const int ko = ks << 5;                  // 8 floats = 32 B per kstep
            uint32_t af[2][4];
#pragma unroll
            for (int mt = 0; mt < 2; mt++) {
                const int a0 = swzA[mt] ^ ko;
                af[mt][0] = *(const uint32_t*)(sA + a0);
                af[mt][1] = *(const uint32_t*)(sA + a0 + 1024);        // row+8
                af[mt][2] = *(const uint32_t*)(sA + (a0 ^ 16));        // k+4
                af[mt][3] = *(const uint32_t*)(sA + ((a0 + 1024) ^ 16));
            }
#pragma unroll
            for (int nt = 0; nt < 4; nt++) {
                const int b0 = swzB[nt] ^ ko;
                uint32_t bf[2];
                bf[0] = *(const uint32_t*)(sB + b0);
                bf[1] = *(const uint32_t*)(sB + (b0 ^ 16));
#pragma unroll
                for (int mt = 0; mt < 2; mt++)
                    mma_tf32(acc[mt][nt], af[mt], bf);
            }
        }
        __syncthreads();                             // protect stage before refill

        const int j = k + 4;
        if (j < nch) {
            char* ld = smem + nxt * STAGE_BYTES;
            load_tile_part(ld,              A, K, m0, j * 32, tid);
            load_tile_part(ld + TILE_BYTES, B, K, n0, j * 32, tid);
        }
        asm volatile("cp.async.commit_group;");      // (possibly empty) keep ledger
        if (++cur == NSTAGE) cur = 0;
        if (++nxt == NSTAGE) nxt = 0;
    }

    // Epilogue: direct STG with bias (c0/c1 -> row, c2/c3 -> row+8)
#pragma unroll
    for (int nt = 0; nt < 4; nt++) {
        const int col = n0 + wn + nt * 8 + cq * 2;
        const float2 b2 = *(const float2*)&bias[col];
#pragma unroll
        for (int mt = 0; mt < 2; mt++) {
            const int row = m0 + wm + mt * 16 + rq;
            float2 v0, v1;
            v0.x = acc[mt][nt][0] + b2.x; v0.y = acc[mt][nt][1] + b2.y;
            v1.x = acc[mt][nt][2] + b2.x; v1.y = acc[mt][nt][3] + b2.y;
            *(float2*)&C[(size_t)row * Ntot + col]       = v0;
            *(float2*)&C[(size_t)(row + 8) * Ntot + col] = v1;
        }
    }
}

// ---------------------------------------------------------------------------
// Windowed attention (fp32), one CTA per (window, head, batch).
// Output rna-rounded to tf32 (feeds the second GEMM's A operand).
// ---------------------------------------------------------------------------
__global__ __launch_bounds__(256)
void win_attn_kernel(const float* __restrict__ qkv, float* __restrict__ out)
{
    extern __shared__ float sm[];
    float* Qs = sm;                 // [64][65]
    float* Ks = Qs + 64 * 65;
    float* Vs = Ks + 64 * 65;
    float* Ps = Vs + 64 * 65;

    const int t = threadIdx.x;
    const int w = blockIdx.x, h = blockIdx.y, b = blockIdx.z;
    const int n0 = w * WIN;
    const size_t base = ((size_t)b * SEQ + n0) * (3 * CDIM) + (size_t)h * HDIM;

#pragma unroll
    for (int i = 0; i < 4; i++) {
        const int e   = t + i * 256;
        const int row = e >> 4;
        const int dc  = (e & 15) * 4;
        const float* src = qkv + base + (size_t)row * (3 * CDIM) + dc;
        const float4 q4 = *(const float4*)(src);
        const float4 k4 = *(const float4*)(src + CDIM);
        const float4 v4 = *(const float4*)(src + 2 * CDIM);
        const int o = row * 65 + dc;
        Qs[o] = q4.x; Qs[o + 1] = q4.y; Qs[o + 2] = q4.z; Qs[o + 3] = q4.w;
        Ks[o] = k4.x; Ks[o + 1] = k4.y; Ks[o + 2] = k4.z; Ks[o + 3] = k4.w;
        Vs[o] = v4.x; Vs[o + 1] = v4.y; Vs[o + 2] = v4.z; Vs[o + 3] = v4.w;
    }
    __syncthreads();

    const int qg = t >> 4;
    const int kg = t & 15;

    float s[4][4];
#pragma unroll
    for (int i = 0; i < 4; i++)
#pragma unroll
        for (int j = 0; j < 4; j++) s[i][j] = 0.f;

#pragma unroll 8
    for (int d = 0; d < 64; d++) {
        float qr[4], kr[4];
#pragma unroll
        for (int i = 0; i < 4; i++) qr[i] = Qs[(qg + 16 * i) * 65 + d];
#pragma unroll
        for (int j = 0; j < 4; j++) kr[j] = Ks[(kg + 16 * j) * 65 + d];
#pragma unroll
        for (int i = 0; i < 4; i++)
#pragma unroll
            for (int j = 0; j < 4; j++)
                s[i][j] = fmaf(qr[i], kr[j], s[i][j]);
    }

    float inv[4];
#pragma unroll
    for (int i = 0; i < 4; i++) {
        float mx = -3.4e38f;
#pragma unroll
        for (int j = 0; j < 4; j++) {
            s[i][j] *= 0.125f;
            mx = fmaxf(mx, s[i][j]);
        }
        mx = fmaxf(mx, __shfl_xor_sync(0xffffffffu, mx, 1));
        mx = fmaxf(mx, __shfl_xor_sync(0xffffffffu, mx, 2));
        mx = fmaxf(mx, __shfl_xor_sync(0xffffffffu, mx, 4));
        mx = fmaxf(mx, __shfl_xor_sync(0xffffffffu, mx, 8));
        float sum = 0.f;
#pragma unroll
        for (int j = 0; j < 4; j++) {
            s[i][j] = __expf(s[i][j] - mx);
            sum += s[i][j];
        }
        sum += __shfl_xor_sync(0xffffffffu, sum, 1);
        sum += __shfl_xor_sync(0xffffffffu, sum, 2);
        sum += __shfl_xor_sync(0xffffffffu, sum, 4);
        sum += __shfl_xor_sync(0xffffffffu, sum, 8);
        inv[i] = 1.f / sum;
#pragma unroll
        for (int j = 0; j < 4; j++)
            Ps[(qg + 16 * i) * 65 + kg + 16 * j] = s[i][j];
    }
    __syncwarp();

    float o[4][4];
#pragma unroll
    for (int i = 0; i < 4; i++)
#pragma unroll
        for (int j = 0; j < 4; j++) o[i][j] = 0.f;

#pragma unroll 8
    for (int k = 0; k < 64; k++) {
        float pr[4], vr[4];
#pragma unroll
        for (int i = 0; i < 4; i++) pr[i] = Ps[(qg + 16 * i) * 65 + k];
#pragma unroll
        for (int j = 0; j < 4; j++) vr[j] = Vs[k * 65 + kg + 16 * j];
#pragma unroll
        for (int i = 0; i < 4; i++)
#pragma unroll
            for (int j = 0; j < 4; j++)
                o[i][j] = fmaf(pr[i], vr[j], o[i][j]);
    }

#pragma unroll
    for (int i = 0; i < 4; i++) {
        const size_t orow = ((size_t)b * SEQ + n0 + qg + 16 * i) * CDIM
                          + (size_t)h * HDIM + kg;
#pragma unroll
        for (int j = 0; j < 4; j++)
            out[orow + 16 * j] = rn_tf32(o[i][j] * inv[i]);
    }
}

// ---------------------------------------------------------------------------
// kernel_launch
// ---------------------------------------------------------------------------
extern "C" void kernel_launch(void* const* d_in, const int* in_sizes, int n_in,
                              void* d_out, int out_size)
{
    const float* x      = (const float*)d_in[0];
    const float* w_qkv  = (const float*)d_in[1];
    const float* b_qkv  = (const float*)d_in[2];
    const float* w_proj = (const float*)d_in[3];
    const float* b_proj = (const float*)d_in[4];
    float* out = (float*)d_out;

    float *xr, *qkv, *attn, *wq_r, *wp_r;
    cudaGetSymbolAddress((void**)&xr,   g_x);
    cudaGetSymbolAddress((void**)&qkv,  g_qkv);
    cudaGetSymbolAddress((void**)&attn, g_attn);
    cudaGetSymbolAddress((void**)&wq_r, g_wqkv_r);
    cudaGetSymbolAddress((void**)&wp_r, g_wproj_r);

    cudaFuncSetAttribute(gemm_tf32,
                         cudaFuncAttributeMaxDynamicSharedMemorySize, GEMM_SMEM);
    const int attn_smem = 4 * 64 * 65 * (int)sizeof(float);
    cudaFuncSetAttribute(win_attn_kernel,
                         cudaFuncAttributeMaxDynamicSharedMemorySize, attn_smem);

    // Pre-passes: rna-round x and weights to the tf32 grid
    const int nwq4 = 3 * CDIM * CDIM / 4, nwp4 = CDIM * CDIM / 4;
    round_tf32_vec<<<(nwq4 + 255) / 256, 256>>>(w_qkv, wq_r, nwq4);
    round_tf32_vec<<<(nwp4 + 255) / 256, 256>>>(w_proj, wp_r, nwp4);
    const int n4 = ROWS * CDIM / 4;
    round_tf32_vec<<<(n4 + 255) / 256, 256>>>(x, xr, n4);

    // 1) QKV projection (tensor cores, mma.sync tf32)
    gemm_tf32<<<dim3(3 * CDIM / 128, ROWS / 128), 512, GEMM_SMEM>>>(
        xr, wq_r, b_qkv, qkv, CDIM, 3 * CDIM);

    // 2) Windowed attention (fp32, tf32-rounded output)
    win_attn_kernel<<<dim3(NWIN, NHEAD, BATCH), 256, attn_smem>>>(qkv, attn);

    // 3) Output projection (tensor cores, mma.sync tf32)
    gemm_tf32<<<dim3(CDIM / 128, ROWS / 128), 512, GEMM_SMEM>>>(
        attn, wp_r, b_proj, out, CDIM, CDIM);
}

// round 10
// speedup vs baseline: 3.3045x; 1.1874x over previous
#include <cuda_runtime.h>
#include <cstdint>

// ---------------------------------------------------------------------------
// HierarchicalAttention on GB300 (sm_103a)
// Round 10 (= round 8 kernel, third submission after two infra timeouts):
// single-pass tf32 mma.sync GEMM, 8 warps x (64x32) warp tile,
// 3-stage cp.async pipeline, 96KB smem -> 2 CTAs/SM. fp32 attention.
// B=4, N=8192, C=1024, H=16, D=64, W=64
// ---------------------------------------------------------------------------

namespace {
constexpr int BATCH = 4;
constexpr int SEQ   = 8192;
constexpr int CDIM  = 1024;
constexpr int NHEAD = 16;
constexpr int HDIM  = 64;
constexpr int WIN   = 64;
constexpr int NWIN  = SEQ / WIN;          // 128
constexpr int ROWS  = BATCH * SEQ;        // 32768

constexpr int TILE_BYTES  = 128 * 32 * 4;             // 16 KB (128 rows x 32 floats)
constexpr int STAGE_BYTES = 2 * TILE_BYTES;           // A + B = 32 KB
constexpr int NSTAGE      = 3;
constexpr int GEMM_SMEM   = NSTAGE * STAGE_BYTES;     // 98,304 B -> 2 CTAs/SM
}

// Scratch (__device__ globals per allocation rules)
__device__ float g_x    [(size_t)ROWS * CDIM];          // rna-tf32-rounded x
__device__ float g_qkv  [(size_t)ROWS * 3 * CDIM];
__device__ float g_attn [(size_t)ROWS * CDIM];          // rna-tf32-rounded attn out
__device__ float g_wqkv_r [(size_t)3 * CDIM * CDIM];    // rna-tf32-rounded weights
__device__ float g_wproj_r[(size_t)CDIM * CDIM];

// ---------------------------------------------------------------------------
// Helpers
// ---------------------------------------------------------------------------
#define SWZ128(x) ((x) ^ (((x) >> 3) & 0x70))

__device__ __forceinline__ void cp_async16(void* dst, const void* src) {
    uint32_t d;
    asm("{ .reg .u64 t; cvta.to.shared.u64 t, %1; cvt.u32.u64 %0, t; }"
        : "=r"(d) : "l"(dst));
    asm volatile("cp.async.cg.shared.global [%0], [%1], 16;" :: "r"(d), "l"(src));
}

__device__ __forceinline__ float rn_tf32(float v) {
    uint32_t u;
    asm("cvt.rna.tf32.f32 %0, %1;" : "=r"(u) : "f"(v));
    return __uint_as_float(u);
}

// mma.sync m16n8k8 tf32: D += A * B   (A row-major 16x8, B col-major 8x8)
__device__ __forceinline__ void mma_tf32(float* c, const uint32_t* a, const uint32_t* b) {
    asm volatile(
        "mma.sync.aligned.m16n8k8.row.col.f32.tf32.tf32.f32 "
        "{%0,%1,%2,%3}, {%4,%5,%6,%7}, {%8,%9}, {%0,%1,%2,%3};"
        : "+f"(c[0]), "+f"(c[1]), "+f"(c[2]), "+f"(c[3])
        : "r"(a[0]), "r"(a[1]), "r"(a[2]), "r"(a[3]), "r"(b[0]), "r"(b[1]));
}

// ---------------------------------------------------------------------------
// Conversion kernels (rna-round to tf32 grid; kills truncation bias in mma)
// ---------------------------------------------------------------------------
__global__ void round_tf32_vec(const float* __restrict__ in, float* __restrict__ outp, int n4) {
    int i = blockIdx.x * blockDim.x + threadIdx.x;
    if (i < n4) {
        float4 v = ((const float4*)in)[i];
        v.x = rn_tf32(v.x); v.y = rn_tf32(v.y);
        v.z = rn_tf32(v.z); v.w = rn_tf32(v.w);
        ((float4*)outp)[i] = v;
    }
}

// ---------------------------------------------------------------------------
// tf32 GEMM (mma.sync): C[m][n] = bias[n] + sum_k A[m][k] * B[n][k]
// Tile 128x128, BK=32 floats, 3-stage cp.async, 8 warps (2x4), 64x32/warp,
// 2 CTAs per SM.
// ---------------------------------------------------------------------------
__device__ __forceinline__ void load_tile_part(char* sbase, const float* __restrict__ g,
                                               int ld, int row0, int kk, int tid) {
#pragma unroll
    for (int i = 0; i < 4; i++) {
        const int e = tid + i * 256;       // 0..1023 granule slots
        const int r = e >> 3;              // row 0..127
        const int c = e & 7;               // 16B granule 0..7
        cp_async16(sbase + SWZ128(r * 128 + c * 16),
                   g + (size_t)(row0 + r) * ld + kk + c * 4);
    }
}

__global__ __launch_bounds__(256, 2)
void gemm_tf32(const float* __restrict__ A, const float* __restrict__ B,
               const float* __restrict__ bias, float* __restrict__ C,
               int K, int Ntot)
{
    extern __shared__ __align__(16) char smem[];
    const int tid  = threadIdx.x;
    const int wid  = tid >> 5;
    const int lane = tid & 31;
    const int m0 = blockIdx.y << 7;
    const int n0 = blockIdx.x << 7;
    const int nch = K >> 5;                          // 32

    const int wm = (wid & 1) * 64;                   // warp m offset in tile
    const int wn = (wid >> 1) * 32;                  // warp n offset in tile
    const int rq = lane >> 2;                        // 0..7
    const int cq = lane & 3;                         // 0..3

    // Swizzled fragment base byte-offsets (kstep/half folded by XOR)
    int swzA[4], swzB[4];
#pragma unroll
    for (int mt = 0; mt < 4; mt++)
        swzA[mt] = SWZ128((wm + mt * 16 + rq) * 128 + cq * 4);
#pragma unroll
    for (int nt = 0; nt < 4; nt++)
        swzB[nt] = SWZ128((wn + nt * 8 + rq) * 128 + cq * 4);

    float acc[4][4][4];
#pragma unroll
    for (int mt = 0; mt < 4; mt++)
#pragma unroll
        for (int nt = 0; nt < 4; nt++)
#pragma unroll
            for (int i = 0; i < 4; i++) acc[mt][nt][i] = 0.f;

    // Prologue: chunks 0..1 -> stages 0..1
#pragma unroll
    for (int j = 0; j < 2; j++) {
        char* st = smem + j * STAGE_BYTES;
        load_tile_part(st,              A, K, m0, j * 32, tid);
        load_tile_part(st + TILE_BYTES, B, K, n0, j * 32, tid);
        asm volatile("cp.async.commit_group;");
    }

    int cur = 0, nxt = 2;                            // stage indices mod 3
    for (int k = 0; k < nch; k++) {
        asm volatile("cp.async.wait_group 1;");      // chunk k resident
        __syncthreads();

        const char* sA = smem + cur * STAGE_BYTES;
        const char* sB = sA + TILE_BYTES;

#pragma unroll
        for (int ks = 0; ks < 4; ks++) {
            const int ko = ks << 5;                  // 8 floats = 32 B per kstep
            uint32_t af[4][4];
#pragma unroll
            for (int mt = 0; mt < 4; mt++) {
                const int a0 = swzA[mt] ^ ko;
                af[mt][0] = *(const uint32_t*)(sA + a0);
                af[mt][1] = *(const uint32_t*)(sA + a0 + 1024);        // row+8
                af[mt][2] = *(const uint32_t*)(sA + (a0 ^ 16));        // k+4
                af[mt][3] = *(const uint32_t*)(sA + ((a0 + 1024) ^ 16));
            }
#pragma unroll
            for (int nt = 0; nt < 4; nt++) {
                const int b0 = swzB[nt] ^ ko;
                uint32_t bf[2];
                bf[0] = *(const uint32_t*)(sB + b0);
                bf[1] = *(const uint32_t*)(sB + (b0 ^ 16));
#pragma unroll
                for (int mt = 0; mt < 4; mt++)
                    mma_tf32(acc[mt][nt], af[mt], bf);
            }
        }
        __syncthreads();                             // protect stage before refill

        const int j = k + 2;
        if (j < nch) {
            char* ld = smem + nxt * STAGE_BYTES;
            load_tile_part(ld,              A, K, m0, j * 32, tid);
            load_tile_part(ld + TILE_BYTES, B, K, n0, j * 32, tid);
        }
        asm volatile("cp.async.commit_group;");      // (possibly empty) keep ledger
        if (++cur == NSTAGE) cur = 0;
        if (++nxt == NSTAGE) nxt = 0;
    }

    // Epilogue: direct STG with bias (c0/c1 -> row, c2/c3 -> row+8)
#pragma unroll
    for (int nt = 0; nt < 4; nt++) {
        const int col = n0 + wn + nt * 8 + cq * 2;
        const float2 b2 = *(const float2*)&bias[col];
#pragma unroll
        for (int mt = 0; mt < 4; mt++) {
            const int row = m0 + wm + mt * 16 + rq;
            float2 v0, v1;
            v0.x = acc[mt][nt][0] + b2.x; v0.y = acc[mt][nt][1] + b2.y;
            v1.x = acc[mt][nt][2] + b2.x; v1.y = acc[mt][nt][3] + b2.y;
            *(float2*)&C[(size_t)row * Ntot + col]       = v0;
            *(float2*)&C[(size_t)(row + 8) * Ntot + col] = v1;
        }
    }
}

// ---------------------------------------------------------------------------
// Windowed attention (fp32), one CTA per (window, head, batch).
// Output rna-rounded to tf32 (feeds the second GEMM's A operand).
// ---------------------------------------------------------------------------
__global__ __launch_bounds__(256)
void win_attn_kernel(const float* __restrict__ qkv, float* __restrict__ out)
{
    extern __shared__ float sm[];
    float* Qs = sm;                 // [64][65]
    float* Ks = Qs + 64 * 65;
    float* Vs = Ks + 64 * 65;
    float* Ps = Vs + 64 * 65;

    const int t = threadIdx.x;
    const int w = blockIdx.x, h = blockIdx.y, b = blockIdx.z;
    const int n0 = w * WIN;
    const size_t base = ((size_t)b * SEQ + n0) * (3 * CDIM) + (size_t)h * HDIM;

#pragma unroll
    for (int i = 0; i < 4; i++) {
        const int e   = t + i * 256;
        const int row = e >> 4;
        const int dc  = (e & 15) * 4;
        const float* src = qkv + base + (size_t)row * (3 * CDIM) + dc;
        const float4 q4 = *(const float4*)(src);
        const float4 k4 = *(const float4*)(src + CDIM);
        const float4 v4 = *(const float4*)(src + 2 * CDIM);
        const int o = row * 65 + dc;
        Qs[o] = q4.x; Qs[o + 1] = q4.y; Qs[o + 2] = q4.z; Qs[o + 3] = q4.w;
        Ks[o] = k4.x; Ks[o + 1] = k4.y; Ks[o + 2] = k4.z; Ks[o + 3] = k4.w;
        Vs[o] = v4.x; Vs[o + 1] = v4.y; Vs[o + 2] = v4.z; Vs[o + 3] = v4.w;
    }
    __syncthreads();

    const int qg = t >> 4;
    const int kg = t & 15;

    float s[4][4];
#pragma unroll
    for (int i = 0; i < 4; i++)
#pragma unroll
        for (int j = 0; j < 4; j++) s[i][j] = 0.f;

#pragma unroll 8
    for (int d = 0; d < 64; d++) {
        float qr[4], kr[4];
#pragma unroll
        for (int i = 0; i < 4; i++) qr[i] = Qs[(qg + 16 * i) * 65 + d];
#pragma unroll
        for (int j = 0; j < 4; j++) kr[j] = Ks[(kg + 16 * j) * 65 + d];
#pragma unroll
        for (int i = 0; i < 4; i++)
#pragma unroll
            for (int j = 0; j < 4; j++)
                s[i][j] = fmaf(qr[i], kr[j], s[i][j]);
    }

    float inv[4];
#pragma unroll
    for (int i = 0; i < 4; i++) {
        float mx = -3.4e38f;
#pragma unroll
        for (int j = 0; j < 4; j++) {
            s[i][j] *= 0.125f;
            mx = fmaxf(mx, s[i][j]);
        }
        mx = fmaxf(mx, __shfl_xor_sync(0xffffffffu, mx, 1));
        mx = fmaxf(mx, __shfl_xor_sync(0xffffffffu, mx, 2));
        mx = fmaxf(mx, __shfl_xor_sync(0xffffffffu, mx, 4));
        mx = fmaxf(mx, __shfl_xor_sync(0xffffffffu, mx, 8));
        float sum = 0.f;
#pragma unroll
        for (int j = 0; j < 4; j++) {
            s[i][j] = __expf(s[i][j] - mx);
            sum += s[i][j];
        }
        sum += __shfl_xor_sync(0xffffffffu, sum, 1);
        sum += __shfl_xor_sync(0xffffffffu, sum, 2);
        sum += __shfl_xor_sync(0xffffffffu, sum, 4);
        sum += __shfl_xor_sync(0xffffffffu, sum, 8);
        inv[i] = 1.f / sum;
#pragma unroll
        for (int j = 0; j < 4; j++)
            Ps[(qg + 16 * i) * 65 + kg + 16 * j] = s[i][j];
    }
    __syncwarp();

    float o[4][4];
#pragma unroll
    for (int i = 0; i < 4; i++)
#pragma unroll
        for (int j = 0; j < 4; j++) o[i][j] = 0.f;

#pragma unroll 8
    for (int k = 0; k < 64; k++) {
        float pr[4], vr[4];
#pragma unroll
        for (int i = 0; i < 4; i++) pr[i] = Ps[(qg + 16 * i) * 65 + k];
#pragma unroll
        for (int j = 0; j < 4; j++) vr[j] = Vs[k * 65 + kg + 16 * j];
#pragma unroll
        for (int i = 0; i < 4; i++)
#pragma unroll
            for (int j = 0; j < 4; j++)
                o[i][j] = fmaf(pr[i], vr[j], o[i][j]);
    }

#pragma unroll
    for (int i = 0; i < 4; i++) {
        const size_t orow = ((size_t)b * SEQ + n0 + qg + 16 * i) * CDIM
                          + (size_t)h * HDIM + kg;
#pragma unroll
        for (int j = 0; j < 4; j++)
            out[orow + 16 * j] = rn_tf32(o[i][j] * inv[i]);
    }
}

// ---------------------------------------------------------------------------
// kernel_launch
// ---------------------------------------------------------------------------
extern "C" void kernel_launch(void* const* d_in, const int* in_sizes, int n_in,
                              void* d_out, int out_size)
{
    const float* x      = (const float*)d_in[0];
    const float* w_qkv  = (const float*)d_in[1];
    const float* b_qkv  = (const float*)d_in[2];
    const float* w_proj = (const float*)d_in[3];
    const float* b_proj = (const float*)d_in[4];
    float* out = (float*)d_out;

    float *xr, *qkv, *attn, *wq_r, *wp_r;
    cudaGetSymbolAddress((void**)&xr,   g_x);
    cudaGetSymbolAddress((void**)&qkv,  g_qkv);
    cudaGetSymbolAddress((void**)&attn, g_attn);
    cudaGetSymbolAddress((void**)&wq_r, g_wqkv_r);
    cudaGetSymbolAddress((void**)&wp_r, g_wproj_r);

    cudaFuncSetAttribute(gemm_tf32,
                         cudaFuncAttributeMaxDynamicSharedMemorySize, GEMM_SMEM);
    const int attn_smem = 4 * 64 * 65 * (int)sizeof(float);
    cudaFuncSetAttribute(win_attn_kernel,
                         cudaFuncAttributeMaxDynamicSharedMemorySize, attn_smem);

    // Pre-passes: rna-round x and weights to the tf32 grid
    const int nwq4 = 3 * CDIM * CDIM / 4, nwp4 = CDIM * CDIM / 4;
    round_tf32_vec<<<(nwq4 + 255) / 256, 256>>>(w_qkv, wq_r, nwq4);
    round_tf32_vec<<<(nwp4 + 255) / 256, 256>>>(w_proj, wp_r, nwp4);
    const int n4 = ROWS * CDIM / 4;
    round_tf32_vec<<<(n4 + 255) / 256, 256>>>(x, xr, n4);

    // 1) QKV projection (tensor cores, mma.sync tf32)
    gemm_tf32<<<dim3(3 * CDIM / 128, ROWS / 128), 256, GEMM_SMEM>>>(
        xr, wq_r, b_qkv, qkv, CDIM, 3 * CDIM);

    // 2) Windowed attention (fp32, tf32-rounded output)
    win_attn_kernel<<<dim3(NWIN, NHEAD, BATCH), 256, attn_smem>>>(qkv, attn);

    // 3) Output projection (tensor cores, mma.sync tf32)
    gemm_tf32<<<dim3(CDIM / 128, ROWS / 128), 256, GEMM_SMEM>>>(
        attn, wp_r, b_proj, out, CDIM, CDIM);
}

// round 12
// speedup vs baseline: 3.3947x; 1.0273x over previous
#include <cuda_runtime.h>
#include <cstdint>

// ---------------------------------------------------------------------------
// HierarchicalAttention on GB300 (sm_103a)
// Round 12 (= round 11 resubmit after infra timeout):
// GEMMs unchanged (round-10 measured config). Windowed attention via
// mma.sync tf32 (K/V hi-lo split => one-sided rounding).
// B=4, N=8192, C=1024, H=16, D=64, W=64
// ---------------------------------------------------------------------------

namespace {
constexpr int BATCH = 4;
constexpr int SEQ   = 8192;
constexpr int CDIM  = 1024;
constexpr int NHEAD = 16;
constexpr int HDIM  = 64;
constexpr int WIN   = 64;
constexpr int NWIN  = SEQ / WIN;          // 128
constexpr int ROWS  = BATCH * SEQ;        // 32768

constexpr int TILE_BYTES  = 128 * 32 * 4;             // 16 KB
constexpr int STAGE_BYTES = 2 * TILE_BYTES;           // A + B = 32 KB
constexpr int NSTAGE      = 3;
constexpr int GEMM_SMEM   = NSTAGE * STAGE_BYTES;     // 98,304 B -> 2 CTAs/SM

constexpr int APITCH    = 68;                         // attn smem pitch (4 mod 32)
constexpr int AMAT      = WIN * APITCH;               // floats per 64x68 array
constexpr int ATTN_SMEM = 6 * AMAT * 4;               // Q,Khi,Klo,Vhi,Vlo,P = 104,448 B
}

// Scratch (__device__ globals per allocation rules)
__device__ float g_x    [(size_t)ROWS * CDIM];          // rna-tf32-rounded x
__device__ float g_qkv  [(size_t)ROWS * 3 * CDIM];
__device__ float g_attn [(size_t)ROWS * CDIM];          // rna-tf32-rounded attn out
__device__ float g_wqkv_r [(size_t)3 * CDIM * CDIM];    // rna-tf32-rounded weights
__device__ float g_wproj_r[(size_t)CDIM * CDIM];

// ---------------------------------------------------------------------------
// Helpers
// ---------------------------------------------------------------------------
#define SWZ128(x) ((x) ^ (((x) >> 3) & 0x70))

__device__ __forceinline__ void cp_async16(void* dst, const void* src) {
    uint32_t d;
    asm("{ .reg .u64 t; cvta.to.shared.u64 t, %1; cvt.u32.u64 %0, t; }"
        : "=r"(d) : "l"(dst));
    asm volatile("cp.async.cg.shared.global [%0], [%1], 16;" :: "r"(d), "l"(src));
}

__device__ __forceinline__ float rn_tf32(float v) {
    uint32_t u;
    asm("cvt.rna.tf32.f32 %0, %1;" : "=r"(u) : "f"(v));
    return __uint_as_float(u);
}

// mma.sync m16n8k8 tf32: D += A * B   (A row-major 16x8, B col-major 8x8)
__device__ __forceinline__ void mma_tf32(float* c, const uint32_t* a, const uint32_t* b) {
    asm volatile(
        "mma.sync.aligned.m16n8k8.row.col.f32.tf32.tf32.f32 "
        "{%0,%1,%2,%3}, {%4,%5,%6,%7}, {%8,%9}, {%0,%1,%2,%3};"
        : "+f"(c[0]), "+f"(c[1]), "+f"(c[2]), "+f"(c[3])
        : "r"(a[0]), "r"(a[1]), "r"(a[2]), "r"(a[3]), "r"(b[0]), "r"(b[1]));
}

__device__ __forceinline__ void mma_tf32_f(float* c, const float* a, const float* b) {
    mma_tf32(c, (const uint32_t*)a, (const uint32_t*)b);
}

// ---------------------------------------------------------------------------
// Conversion kernels (rna-round to tf32 grid)
// ---------------------------------------------------------------------------
__global__ void round_tf32_vec(const float* __restrict__ in, float* __restrict__ outp, int n4) {
    int i = blockIdx.x * blockDim.x + threadIdx.x;
    if (i < n4) {
        float4 v = ((const float4*)in)[i];
        v.x = rn_tf32(v.x); v.y = rn_tf32(v.y);
        v.z = rn_tf32(v.z); v.w = rn_tf32(v.w);
        ((float4*)outp)[i] = v;
    }
}

// ---------------------------------------------------------------------------
// tf32 GEMM (mma.sync): unchanged from round 10 (measured: 63.4% tensor).
// ---------------------------------------------------------------------------
__device__ __forceinline__ void load_tile_part(char* sbase, const float* __restrict__ g,
                                               int ld, int row0, int kk, int tid) {
#pragma unroll
    for (int i = 0; i < 4; i++) {
        const int e = tid + i * 256;
        const int r = e >> 3;
        const int c = e & 7;
        cp_async16(sbase + SWZ128(r * 128 + c * 16),
                   g + (size_t)(row0 + r) * ld + kk + c * 4);
    }
}

__global__ __launch_bounds__(256, 2)
void gemm_tf32(const float* __restrict__ A, const float* __restrict__ B,
               const float* __restrict__ bias, float* __restrict__ C,
               int K, int Ntot)
{
    extern __shared__ __align__(16) char smem[];
    const int tid  = threadIdx.x;
    const int wid  = tid >> 5;
    const int lane = tid & 31;
    const int m0 = blockIdx.y << 7;
    const int n0 = blockIdx.x << 7;
    const int nch = K >> 5;

    const int wm = (wid & 1) * 64;
    const int wn = (wid >> 1) * 32;
    const int rq = lane >> 2;
    const int cq = lane & 3;

    int swzA[4], swzB[4];
#pragma unroll
    for (int mt = 0; mt < 4; mt++)
        swzA[mt] = SWZ128((wm + mt * 16 + rq) * 128 + cq * 4);
#pragma unroll
    for (int nt = 0; nt < 4; nt++)
        swzB[nt] = SWZ128((wn + nt * 8 + rq) * 128 + cq * 4);

    float acc[4][4][4];
#pragma unroll
    for (int mt = 0; mt < 4; mt++)
#pragma unroll
        for (int nt = 0; nt < 4; nt++)
#pragma unroll
            for (int i = 0; i < 4; i++) acc[mt][nt][i] = 0.f;

#pragma unroll
    for (int j = 0; j < 2; j++) {
        char* st = smem + j * STAGE_BYTES;
        load_tile_part(st,              A, K, m0, j * 32, tid);
        load_tile_part(st + TILE_BYTES, B, K, n0, j * 32, tid);
        asm volatile("cp.async.commit_group;");
    }

    int cur = 0, nxt = 2;
    for (int k = 0; k < nch; k++) {
        asm volatile("cp.async.wait_group 1;");
        __syncthreads();

        const char* sA = smem + cur * STAGE_BYTES;
        const char* sB = sA + TILE_BYTES;

#pragma unroll
        for (int ks = 0; ks < 4; ks++) {
            const int ko = ks << 5;
            uint32_t af[4][4];
#pragma unroll
            for (int mt = 0; mt < 4; mt++) {
                const int a0 = swzA[mt] ^ ko;
                af[mt][0] = *(const uint32_t*)(sA + a0);
                af[mt][1] = *(const uint32_t*)(sA + a0 + 1024);
                af[mt][2] = *(const uint32_t*)(sA + (a0 ^ 16));
                af[mt][3] = *(const uint32_t*)(sA + ((a0 + 1024) ^ 16));
            }
#pragma unroll
            for (int nt = 0; nt < 4; nt++) {
                const int b0 = swzB[nt] ^ ko;
                uint32_t bf[2];
                bf[0] = *(const uint32_t*)(sB + b0);
                bf[1] = *(const uint32_t*)(sB + (b0 ^ 16));
#pragma unroll
                for (int mt = 0; mt < 4; mt++)
                    mma_tf32(acc[mt][nt], af[mt], bf);
            }
        }
        __syncthreads();

        const int j = k + 2;
        if (j < nch) {
            char* ld = smem + nxt * STAGE_BYTES;
            load_tile_part(ld,              A, K, m0, j * 32, tid);
            load_tile_part(ld + TILE_BYTES, B, K, n0, j * 32, tid);
        }
        asm volatile("cp.async.commit_group;");
        if (++cur == NSTAGE) cur = 0;
        if (++nxt == NSTAGE) nxt = 0;
    }

#pragma unroll
    for (int nt = 0; nt < 4; nt++) {
        const int col = n0 + wn + nt * 8 + cq * 2;
        const float2 b2 = *(const float2*)&bias[col];
#pragma unroll
        for (int mt = 0; mt < 4; mt++) {
            const int row = m0 + wm + mt * 16 + rq;
            float2 v0, v1;
            v0.x = acc[mt][nt][0] + b2.x; v0.y = acc[mt][nt][1] + b2.y;
            v1.x = acc[mt][nt][2] + b2.x; v1.y = acc[mt][nt][3] + b2.y;
            *(float2*)&C[(size_t)row * Ntot + col]       = v0;
            *(float2*)&C[(size_t)(row + 8) * Ntot + col] = v1;
        }
    }
}

// ---------------------------------------------------------------------------
// Windowed attention via mma.sync tf32.
// One CTA (256 thr, 8 warps) per (window, head, batch).
// Warp (wid&3, wid>>2) computes rows (wid&3)*16..+15, cols (wid>>2)*32..+31
// of both S = (Q*0.125) K^T and O = P V.
// K and V are hi/lo tf32-split in smem (exact B operand); Q and P rounded
// once (one-sided error per attention GEMM). V stored transposed [d][token].
// ---------------------------------------------------------------------------
__global__ __launch_bounds__(256)
void win_attn_mma(const float* __restrict__ qkv, float* __restrict__ out)
{
    extern __shared__ float sm[];
    float* Qs  = sm;               // [64][68], pre-scaled & rounded
    float* Khi = sm + AMAT;        // [n=token][k=d]
    float* Klo = sm + 2 * AMAT;
    float* Vhi = sm + 3 * AMAT;    // transposed: [n=d][k=token]
    float* Vlo = sm + 4 * AMAT;
    float* Ps  = sm + 5 * AMAT;    // [m=query][k=token]

    const int tid  = threadIdx.x;
    const int wid  = tid >> 5;
    const int lane = tid & 31;
    const int w = blockIdx.x, h = blockIdx.y, b = blockIdx.z;
    const int n0 = w * WIN;
    const size_t base = ((size_t)b * SEQ + n0) * (3 * CDIM) + (size_t)h * HDIM;

    // ---- Load Q (scaled+rounded), K hi/lo, V hi/lo (transposed) ----
#pragma unroll
    for (int i = 0; i < 4; i++) {
        const int e   = tid + i * 256;          // 0..1023
        const int row = e >> 4;                 // token 0..63
        const int dc  = (e & 15) * 4;           // d offset
        const float* src = qkv + base + (size_t)row * (3 * CDIM) + dc;
        const float4 q4 = *(const float4*)(src);
        const float4 k4 = *(const float4*)(src + CDIM);
        const float4 v4 = *(const float4*)(src + 2 * CDIM);
        const int o = row * APITCH + dc;

        float4 qr;
        qr.x = rn_tf32(q4.x * 0.125f); qr.y = rn_tf32(q4.y * 0.125f);
        qr.z = rn_tf32(q4.z * 0.125f); qr.w = rn_tf32(q4.w * 0.125f);
        *(float4*)&Qs[o] = qr;

        float4 kh, kl;
        kh.x = rn_tf32(k4.x); kl.x = rn_tf32(k4.x - kh.x);
        kh.y = rn_tf32(k4.y); kl.y = rn_tf32(k4.y - kh.y);
        kh.z = rn_tf32(k4.z); kl.z = rn_tf32(k4.z - kh.z);
        kh.w = rn_tf32(k4.w); kl.w = rn_tf32(k4.w - kh.w);
        *(float4*)&Khi[o] = kh;
        *(float4*)&Klo[o] = kl;

        const float vv[4] = {v4.x, v4.y, v4.z, v4.w};
#pragma unroll
        for (int j = 0; j < 4; j++) {
            const float hv = rn_tf32(vv[j]);
            Vhi[(dc + j) * APITCH + row] = hv;
            Vlo[(dc + j) * APITCH + row] = rn_tf32(vv[j] - hv);
        }
    }
    __syncthreads();

    const int m0w = (wid & 3) * 16;             // warp query-row base
    const int nh  = (wid >> 2) * 32;            // warp col base
    const int rq  = lane >> 2;
    const int cq  = lane & 3;

    // ---- S = Q K^T (K split: exact B side) ----
    {
        float sacc[4][4];
#pragma unroll
        for (int nt = 0; nt < 4; nt++)
#pragma unroll
            for (int i = 0; i < 4; i++) sacc[nt][i] = 0.f;

#pragma unroll
        for (int ks = 0; ks < 8; ks++) {
            const int ko = ks * 8;
            float af[4];
            af[0] = Qs[(m0w + rq)     * APITCH + ko + cq];
            af[1] = Qs[(m0w + rq + 8) * APITCH + ko + cq];
            af[2] = Qs[(m0w + rq)     * APITCH + ko + cq + 4];
            af[3] = Qs[(m0w + rq + 8) * APITCH + ko + cq + 4];
#pragma unroll
            for (int nt = 0; nt < 4; nt++) {
                const int nrow = (nh + nt * 8 + rq) * APITCH + ko + cq;
                float bh[2], bl[2];
                bh[0] = Khi[nrow]; bh[1] = Khi[nrow + 4];
                bl[0] = Klo[nrow]; bl[1] = Klo[nrow + 4];
                mma_tf32_f(sacc[nt], af, bh);
                mma_tf32_f(sacc[nt], af, bl);
            }
        }
        // store S tile to Ps
#pragma unroll
        for (int nt = 0; nt < 4; nt++) {
            const int col = nh + nt * 8 + cq * 2;
            *(float2*)&Ps[(m0w + rq)     * APITCH + col] = make_float2(sacc[nt][0], sacc[nt][1]);
            *(float2*)&Ps[(m0w + rq + 8) * APITCH + col] = make_float2(sacc[nt][2], sacc[nt][3]);
        }
    }
    __syncthreads();

    // ---- softmax over rows of Ps (4 threads per row, 16 cols each);
    //      1/sum folded into P, result rounded to tf32 (A side of PV) ----
    {
        const int row = tid >> 2;
        const int seg = tid & 3;
        float* pr = Ps + row * APITCH + seg * 16;
        float v[16];
#pragma unroll
        for (int i = 0; i < 4; i++) {
            const float4 t = *(const float4*)&pr[i * 4];
            v[i*4+0] = t.x; v[i*4+1] = t.y; v[i*4+2] = t.z; v[i*4+3] = t.w;
        }
        float mx = v[0];
#pragma unroll
        for (int i = 1; i < 16; i++) mx = fmaxf(mx, v[i]);
        mx = fmaxf(mx, __shfl_xor_sync(0xffffffffu, mx, 1));
        mx = fmaxf(mx, __shfl_xor_sync(0xffffffffu, mx, 2));
        float sum = 0.f;
#pragma unroll
        for (int i = 0; i < 16; i++) { v[i] = __expf(v[i] - mx); sum += v[i]; }
        sum += __shfl_xor_sync(0xffffffffu, sum, 1);
        sum += __shfl_xor_sync(0xffffffffu, sum, 2);
        const float inv = 1.f / sum;
#pragma unroll
        for (int i = 0; i < 4; i++) {
            float4 t;
            t.x = rn_tf32(v[i*4+0] * inv); t.y = rn_tf32(v[i*4+1] * inv);
            t.z = rn_tf32(v[i*4+2] * inv); t.w = rn_tf32(v[i*4+3] * inv);
            *(float4*)&pr[i * 4] = t;
        }
    }
    __syncthreads();

    // ---- O = P V (V split: exact B side); write rounded to out ----
    {
        float oacc[4][4];
#pragma unroll
        for (int nt = 0; nt < 4; nt++)
#pragma unroll
            for (int i = 0; i < 4; i++) oacc[nt][i] = 0.f;

#pragma unroll
        for (int ks = 0; ks < 8; ks++) {
            const int ko = ks * 8;
            float af[4];
            af[0] = Ps[(m0w + rq)     * APITCH + ko + cq];
            af[1] = Ps[(m0w + rq + 8) * APITCH + ko + cq];
            af[2] = Ps[(m0w + rq)     * APITCH + ko + cq + 4];
            af[3] = Ps[(m0w + rq + 8) * APITCH + ko + cq + 4];
#pragma unroll
            for (int nt = 0; nt < 4; nt++) {
                const int nrow = (nh + nt * 8 + rq) * APITCH + ko + cq;
                float bh[2], bl[2];
                bh[0] = Vhi[nrow]; bh[1] = Vhi[nrow + 4];
                bl[0] = Vlo[nrow]; bl[1] = Vlo[nrow + 4];
                mma_tf32_f(oacc[nt], af, bh);
                mma_tf32_f(oacc[nt], af, bl);
            }
        }

        const size_t row0 = (size_t)b * SEQ + n0 + m0w + rq;
#pragma unroll
        for (int nt = 0; nt < 4; nt++) {
            const int col = h * HDIM + nh + nt * 8 + cq * 2;
            float2 v0, v1;
            v0.x = rn_tf32(oacc[nt][0]); v0.y = rn_tf32(oacc[nt][1]);
            v1.x = rn_tf32(oacc[nt][2]); v1.y = rn_tf32(oacc[nt][3]);
            *(float2*)&out[row0 * CDIM + col]       = v0;
            *(float2*)&out[(row0 + 8) * CDIM + col] = v1;
        }
    }
}

// ---------------------------------------------------------------------------
// kernel_launch
// ---------------------------------------------------------------------------
extern "C" void kernel_launch(void* const* d_in, const int* in_sizes, int n_in,
                              void* d_out, int out_size)
{
    const float* x      = (const float*)d_in[0];
    const float* w_qkv  = (const float*)d_in[1];
    const float* b_qkv  = (const float*)d_in[2];
    const float* w_proj = (const float*)d_in[3];
    const float* b_proj = (const float*)d_in[4];
    float* out = (float*)d_out;

    float *xr, *qkv, *attn, *wq_r, *wp_r;
    cudaGetSymbolAddress((void**)&xr,   g_x);
    cudaGetSymbolAddress((void**)&qkv,  g_qkv);
    cudaGetSymbolAddress((void**)&attn, g_attn);
    cudaGetSymbolAddress((void**)&wq_r, g_wqkv_r);
    cudaGetSymbolAddress((void**)&wp_r, g_wproj_r);

    cudaFuncSetAttribute(gemm_tf32,
                         cudaFuncAttributeMaxDynamicSharedMemorySize, GEMM_SMEM);
    cudaFuncSetAttribute(win_attn_mma,
                         cudaFuncAttributeMaxDynamicSharedMemorySize, ATTN_SMEM);

    // Pre-passes: rna-round x and weights to the tf32 grid
    const int nwq4 = 3 * CDIM * CDIM / 4, nwp4 = CDIM * CDIM / 4;
    round_tf32_vec<<<(nwq4 + 255) / 256, 256>>>(w_qkv, wq_r, nwq4);
    round_tf32_vec<<<(nwp4 + 255) / 256, 256>>>(w_proj, wp_r, nwp4);
    const int n4 = ROWS * CDIM / 4;
    round_tf32_vec<<<(n4 + 255) / 256, 256>>>(x, xr, n4);

    // 1) QKV projection (tensor cores, mma.sync tf32)
    gemm_tf32<<<dim3(3 * CDIM / 128, ROWS / 128), 256, GEMM_SMEM>>>(
        xr, wq_r, b_qkv, qkv, CDIM, 3 * CDIM);

    // 2) Windowed attention (mma.sync tf32, K/V hi-lo split)
    win_attn_mma<<<dim3(NWIN, NHEAD, BATCH), 256, ATTN_SMEM>>>(qkv, attn);

    // 3) Output projection (tensor cores, mma.sync tf32)
    gemm_tf32<<<dim3(CDIM / 128, ROWS / 128), 256, GEMM_SMEM>>>(
        attn, wp_r, b_proj, out, CDIM, CDIM);
}

// round 15
// speedup vs baseline: 3.4569x; 1.0183x over previous
#include <cuda_runtime.h>
#include <cstdint>

// ---------------------------------------------------------------------------
// HierarchicalAttention on GB300 (sm_103a)
// Round 15 (= round 13 kernel, third submission after two infra timeouts):
// GEMM mainloop restructured — redundant per-chunk barrier removed,
// refill hoisted before compute (loads fly during MMAs). Numerics untouched.
// Attention = round-12 measured mma.sync version.
// B=4, N=8192, C=1024, H=16, D=64, W=64
// ---------------------------------------------------------------------------

namespace {
constexpr int BATCH = 4;
constexpr int SEQ   = 8192;
constexpr int CDIM  = 1024;
constexpr int NHEAD = 16;
constexpr int HDIM  = 64;
constexpr int WIN   = 64;
constexpr int NWIN  = SEQ / WIN;          // 128
constexpr int ROWS  = BATCH * SEQ;        // 32768

constexpr int TILE_BYTES  = 128 * 32 * 4;             // 16 KB
constexpr int STAGE_BYTES = 2 * TILE_BYTES;           // A + B = 32 KB
constexpr int NSTAGE      = 3;
constexpr int GEMM_SMEM   = NSTAGE * STAGE_BYTES;     // 98,304 B -> 2 CTAs/SM

constexpr int APITCH    = 68;                         // attn smem pitch (4 mod 32)
constexpr int AMAT      = WIN * APITCH;               // floats per 64x68 array
constexpr int ATTN_SMEM = 6 * AMAT * 4;               // Q,Khi,Klo,Vhi,Vlo,P = 104,448 B
}

// Scratch (__device__ globals per allocation rules)
__device__ float g_x    [(size_t)ROWS * CDIM];          // rna-tf32-rounded x
__device__ float g_qkv  [(size_t)ROWS * 3 * CDIM];
__device__ float g_attn [(size_t)ROWS * CDIM];          // attn out (tf32-rounded)
__device__ float g_wqkv_r [(size_t)3 * CDIM * CDIM];    // rna-tf32-rounded weights
__device__ float g_wproj_r[(size_t)CDIM * CDIM];

// ---------------------------------------------------------------------------
// Helpers
// ---------------------------------------------------------------------------
#define SWZ128(x) ((x) ^ (((x) >> 3) & 0x70))

__device__ __forceinline__ void cp_async16(void* dst, const void* src) {
    uint32_t d;
    asm("{ .reg .u64 t; cvta.to.shared.u64 t, %1; cvt.u32.u64 %0, t; }"
        : "=r"(d) : "l"(dst));
    asm volatile("cp.async.cg.shared.global [%0], [%1], 16;" :: "r"(d), "l"(src));
}

__device__ __forceinline__ float rn_tf32(float v) {
    uint32_t u;
    asm("cvt.rna.tf32.f32 %0, %1;" : "=r"(u) : "f"(v));
    return __uint_as_float(u);
}

// mma.sync m16n8k8 tf32: D += A * B   (A row-major 16x8, B col-major 8x8)
__device__ __forceinline__ void mma_tf32(float* c, const uint32_t* a, const uint32_t* b) {
    asm volatile(
        "mma.sync.aligned.m16n8k8.row.col.f32.tf32.tf32.f32 "
        "{%0,%1,%2,%3}, {%4,%5,%6,%7}, {%8,%9}, {%0,%1,%2,%3};"
        : "+f"(c[0]), "+f"(c[1]), "+f"(c[2]), "+f"(c[3])
        : "r"(a[0]), "r"(a[1]), "r"(a[2]), "r"(a[3]), "r"(b[0]), "r"(b[1]));
}

__device__ __forceinline__ void mma_tf32_f(float* c, const float* a, const float* b) {
    mma_tf32(c, (const uint32_t*)a, (const uint32_t*)b);
}

// ---------------------------------------------------------------------------
// Conversion kernels (rna-round to tf32 grid)
// ---------------------------------------------------------------------------
__global__ void round_tf32_vec(const float* __restrict__ in, float* __restrict__ outp, int n4) {
    int i = blockIdx.x * blockDim.x + threadIdx.x;
    if (i < n4) {
        float4 v = ((const float4*)in)[i];
        v.x = rn_tf32(v.x); v.y = rn_tf32(v.y);
        v.z = rn_tf32(v.z); v.w = rn_tf32(v.w);
        ((float4*)outp)[i] = v;
    }
}

// ---------------------------------------------------------------------------
// tf32 GEMM (mma.sync): C[m][n] = bias[n] + sum_k A[m][k] * B[n][k]
// Tile 128x128, BK=32, 3-stage cp.async, 8 warps (64x32/warp), 2 CTAs/SM.
// Refill hoisted before compute; single barrier per chunk.
// ---------------------------------------------------------------------------
__device__ __forceinline__ void load_tile_part(char* sbase, const float* __restrict__ g,
                                               int ld, int row0, int kk, int tid) {
#pragma unroll
    for (int i = 0; i < 4; i++) {
        const int e = tid + i * 256;
        const int r = e >> 3;
        const int c = e & 7;
        cp_async16(sbase + SWZ128(r * 128 + c * 16),
                   g + (size_t)(row0 + r) * ld + kk + c * 4);
    }
}

__global__ __launch_bounds__(256, 2)
void gemm_tf32(const float* __restrict__ A, const float* __restrict__ B,
               const float* __restrict__ bias, float* __restrict__ C,
               int K, int Ntot)
{
    extern __shared__ __align__(16) char smem[];
    const int tid  = threadIdx.x;
    const int wid  = tid >> 5;
    const int lane = tid & 31;
    const int m0 = blockIdx.y << 7;
    const int n0 = blockIdx.x << 7;
    const int nch = K >> 5;

    const int wm = (wid & 1) * 64;
    const int wn = (wid >> 1) * 32;
    const int rq = lane >> 2;
    const int cq = lane & 3;

    int swzA[4], swzB[4];
#pragma unroll
    for (int mt = 0; mt < 4; mt++)
        swzA[mt] = SWZ128((wm + mt * 16 + rq) * 128 + cq * 4);
#pragma unroll
    for (int nt = 0; nt < 4; nt++)
        swzB[nt] = SWZ128((wn + nt * 8 + rq) * 128 + cq * 4);

    float acc[4][4][4];
#pragma unroll
    for (int mt = 0; mt < 4; mt++)
#pragma unroll
        for (int nt = 0; nt < 4; nt++)
#pragma unroll
            for (int i = 0; i < 4; i++) acc[mt][nt][i] = 0.f;

    // Prologue: chunks 0..1 -> stages 0..1
#pragma unroll
    for (int j = 0; j < 2; j++) {
        char* st = smem + j * STAGE_BYTES;
        load_tile_part(st,              A, K, m0, j * 32, tid);
        load_tile_part(st + TILE_BYTES, B, K, n0, j * 32, tid);
        asm volatile("cp.async.commit_group;");
    }

    int cur = 0, nxt = 2;
    for (int k = 0; k < nch; k++) {
        asm volatile("cp.async.wait_group 1;");      // chunk k resident
        __syncthreads();                             // (also orders iter k-1 reads
                                                     //  of stage nxt before refill)
        // Refill FIRST: chunk k+2 flies while we compute chunk k.
        const int j = k + 2;
        if (j < nch) {
            char* ld = smem + nxt * STAGE_BYTES;
            load_tile_part(ld,              A, K, m0, j * 32, tid);
            load_tile_part(ld + TILE_BYTES, B, K, n0, j * 32, tid);
        }
        asm volatile("cp.async.commit_group;");      // (possibly empty) keep ledger

        const char* sA = smem + cur * STAGE_BYTES;
        const char* sB = sA + TILE_BYTES;

#pragma unroll
        for (int ks = 0; ks < 4; ks++) {
            const int ko = ks << 5;
            uint32_t af[4][4];
#pragma unroll
            for (int mt = 0; mt < 4; mt++) {
                const int a0 = swzA[mt] ^ ko;
                af[mt][0] = *(const uint32_t*)(sA + a0);
                af[mt][1] = *(const uint32_t*)(sA + a0 + 1024);
                af[mt][2] = *(const uint32_t*)(sA + (a0 ^ 16));
                af[mt][3] = *(const uint32_t*)(sA + ((a0 + 1024) ^ 16));
            }
#pragma unroll
            for (int nt = 0; nt < 4; nt++) {
                const int b0 = swzB[nt] ^ ko;
                uint32_t bf[2];
                bf[0] = *(const uint32_t*)(sB + b0);
                bf[1] = *(const uint32_t*)(sB + (b0 ^ 16));
#pragma unroll
                for (int mt = 0; mt < 4; mt++)
                    mma_tf32(acc[mt][nt], af[mt], bf);
            }
        }

        if (++cur == NSTAGE) cur = 0;
        if (++nxt == NSTAGE) nxt = 0;
    }

    // Epilogue: direct STG with bias (c0/c1 -> row, c2/c3 -> row+8)
#pragma unroll
    for (int nt = 0; nt < 4; nt++) {
        const int col = n0 + wn + nt * 8 + cq * 2;
        const float2 b2 = *(const float2*)&bias[col];
#pragma unroll
        for (int mt = 0; mt < 4; mt++) {
            const int row = m0 + wm + mt * 16 + rq;
            float2 v0, v1;
            v0.x = acc[mt][nt][0] + b2.x; v0.y = acc[mt][nt][1] + b2.y;
            v1.x = acc[mt][nt][2] + b2.x; v1.y = acc[mt][nt][3] + b2.y;
            *(float2*)&C[(size_t)row * Ntot + col]       = v0;
            *(float2*)&C[(size_t)(row + 8) * Ntot + col] = v1;
        }
    }
}

// ---------------------------------------------------------------------------
// Windowed attention via mma.sync tf32 (unchanged from round 12, measured).
// ---------------------------------------------------------------------------
__global__ __launch_bounds__(256)
void win_attn_mma(const float* __restrict__ qkv, float* __restrict__ out)
{
    extern __shared__ float sm[];
    float* Qs  = sm;               // [64][68], pre-scaled & rounded
    float* Khi = sm + AMAT;        // [n=token][k=d]
    float* Klo = sm + 2 * AMAT;
    float* Vhi = sm + 3 * AMAT;    // transposed: [n=d][k=token]
    float* Vlo = sm + 4 * AMAT;
    float* Ps  = sm + 5 * AMAT;    // [m=query][k=token]

    const int tid  = threadIdx.x;
    const int wid  = tid >> 5;
    const int lane = tid & 31;
    const int w = blockIdx.x, h = blockIdx.y, b = blockIdx.z;
    const int n0 = w * WIN;
    const size_t base = ((size_t)b * SEQ + n0) * (3 * CDIM) + (size_t)h * HDIM;

#pragma unroll
    for (int i = 0; i < 4; i++) {
        const int e   = tid + i * 256;
        const int row = e >> 4;
        const int dc  = (e & 15) * 4;
        const float* src = qkv + base + (size_t)row * (3 * CDIM) + dc;
        const float4 q4 = *(const float4*)(src);
        const float4 k4 = *(const float4*)(src + CDIM);
        const float4 v4 = *(const float4*)(src + 2 * CDIM);
        const int o = row * APITCH + dc;

        float4 qr;
        qr.x = rn_tf32(q4.x * 0.125f); qr.y = rn_tf32(q4.y * 0.125f);
        qr.z = rn_tf32(q4.z * 0.125f); qr.w = rn_tf32(q4.w * 0.125f);
        *(float4*)&Qs[o] = qr;

        float4 kh, kl;
        kh.x = rn_tf32(k4.x); kl.x = rn_tf32(k4.x - kh.x);
        kh.y = rn_tf32(k4.y); kl.y = rn_tf32(k4.y - kh.y);
        kh.z = rn_tf32(k4.z); kl.z = rn_tf32(k4.z - kh.z);
        kh.w = rn_tf32(k4.w); kl.w = rn_tf32(k4.w - kh.w);
        *(float4*)&Khi[o] = kh;
        *(float4*)&Klo[o] = kl;

        const float vv[4] = {v4.x, v4.y, v4.z, v4.w};
#pragma unroll
        for (int j = 0; j < 4; j++) {
            const float hv = rn_tf32(vv[j]);
            Vhi[(dc + j) * APITCH + row] = hv;
            Vlo[(dc + j) * APITCH + row] = rn_tf32(vv[j] - hv);
        }
    }
    __syncthreads();

    const int m0w = (wid & 3) * 16;
    const int nh  = (wid >> 2) * 32;
    const int rq  = lane >> 2;
    const int cq  = lane & 3;

    // ---- S = Q K^T (K split: exact B side) ----
    {
        float sacc[4][4];
#pragma unroll
        for (int nt = 0; nt < 4; nt++)
#pragma unroll
            for (int i = 0; i < 4; i++) sacc[nt][i] = 0.f;

#pragma unroll
        for (int ks = 0; ks < 8; ks++) {
            const int ko = ks * 8;
            float af[4];
            af[0] = Qs[(m0w + rq)     * APITCH + ko + cq];
            af[1] = Qs[(m0w + rq + 8) * APITCH + ko + cq];
            af[2] = Qs[(m0w + rq)     * APITCH + ko + cq + 4];
            af[3] = Qs[(m0w + rq + 8) * APITCH + ko + cq + 4];
#pragma unroll
            for (int nt = 0; nt < 4; nt++) {
                const int nrow = (nh + nt * 8 + rq) * APITCH + ko + cq;
                float bh[2], bl[2];
                bh[0] = Khi[nrow]; bh[1] = Khi[nrow + 4];
                bl[0] = Klo[nrow]; bl[1] = Klo[nrow + 4];
                mma_tf32_f(sacc[nt], af, bh);
                mma_tf32_f(sacc[nt], af, bl);
            }
        }
#pragma unroll
        for (int nt = 0; nt < 4; nt++) {
            const int col = nh + nt * 8 + cq * 2;
            *(float2*)&Ps[(m0w + rq)     * APITCH + col] = make_float2(sacc[nt][0], sacc[nt][1]);
            *(float2*)&Ps[(m0w + rq + 8) * APITCH + col] = make_float2(sacc[nt][2], sacc[nt][3]);
        }
    }
    __syncthreads();

    // ---- softmax over rows of Ps; 1/sum folded, result tf32-rounded ----
    {
        const int row = tid >> 2;
        const int seg = tid & 3;
        float* pr = Ps + row * APITCH + seg * 16;
        float v[16];
#pragma unroll
        for (int i = 0; i < 4; i++) {
            const float4 t = *(const float4*)&pr[i * 4];
            v[i*4+0] = t.x; v[i*4+1] = t.y; v[i*4+2] = t.z; v[i*4+3] = t.w;
        }
        float mx = v[0];
#pragma unroll
        for (int i = 1; i < 16; i++) mx = fmaxf(mx, v[i]);
        mx = fmaxf(mx, __shfl_xor_sync(0xffffffffu, mx, 1));
        mx = fmaxf(mx, __shfl_xor_sync(0xffffffffu, mx, 2));
        float sum = 0.f;
#pragma unroll
        for (int i = 0; i < 16; i++) { v[i] = __expf(v[i] - mx); sum += v[i]; }
        sum += __shfl_xor_sync(0xffffffffu, sum, 1);
        sum += __shfl_xor_sync(0xffffffffu, sum, 2);
        const float inv = 1.f / sum;
#pragma unroll
        for (int i = 0; i < 4; i++) {
            float4 t;
            t.x = rn_tf32(v[i*4+0] * inv); t.y = rn_tf32(v[i*4+1] * inv);
            t.z = rn_tf32(v[i*4+2] * inv); t.w = rn_tf32(v[i*4+3] * inv);
            *(float4*)&pr[i * 4] = t;
        }
    }
    __syncthreads();

    // ---- O = P V (V split: exact B side); write rounded to out ----
    {
        float oacc[4][4];
#pragma unroll
        for (int nt = 0; nt < 4; nt++)
#pragma unroll
            for (int i = 0; i < 4; i++) oacc[nt][i] = 0.f;

#pragma unroll
        for (int ks = 0; ks < 8; ks++) {
            const int ko = ks * 8;
            float af[4];
            af[0] = Ps[(m0w + rq)     * APITCH + ko + cq];
            af[1] = Ps[(m0w + rq + 8) * APITCH + ko + cq];
            af[2] = Ps[(m0w + rq)     * APITCH + ko + cq + 4];
            af[3] = Ps[(m0w + rq + 8) * APITCH + ko + cq + 4];
#pragma unroll
            for (int nt = 0; nt < 4; nt++) {
                const int nrow = (nh + nt * 8 + rq) * APITCH + ko + cq;
                float bh[2], bl[2];
                bh[0] = Vhi[nrow]; bh[1] = Vhi[nrow + 4];
                bl[0] = Vlo[nrow]; bl[1] = Vlo[nrow + 4];
                mma_tf32_f(oacc[nt], af, bh);
                mma_tf32_f(oacc[nt], af, bl);
            }
        }

        const size_t row0 = (size_t)b * SEQ + n0 + m0w + rq;
#pragma unroll
        for (int nt = 0; nt < 4; nt++) {
            const int col = h * HDIM + nh + nt * 8 + cq * 2;
            float2 v0, v1;
            v0.x = rn_tf32(oacc[nt][0]); v0.y = rn_tf32(oacc[nt][1]);
            v1.x = rn_tf32(oacc[nt][2]); v1.y = rn_tf32(oacc[nt][3]);
            *(float2*)&out[row0 * CDIM + col]       = v0;
            *(float2*)&out[(row0 + 8) * CDIM + col] = v1;
        }
    }
}

// ---------------------------------------------------------------------------
// kernel_launch
// ---------------------------------------------------------------------------
extern "C" void kernel_launch(void* const* d_in, const int* in_sizes, int n_in,
                              void* d_out, int out_size)
{
    const float* x      = (const float*)d_in[0];
    const float* w_qkv  = (const float*)d_in[1];
    const float* b_qkv  = (const float*)d_in[2];
    const float* w_proj = (const float*)d_in[3];
    const float* b_proj = (const float*)d_in[4];
    float* out = (float*)d_out;

    float *xr, *qkv, *attn, *wq_r, *wp_r;
    cudaGetSymbolAddress((void**)&xr,   g_x);
    cudaGetSymbolAddress((void**)&qkv,  g_qkv);
    cudaGetSymbolAddress((void**)&attn, g_attn);
    cudaGetSymbolAddress((void**)&wq_r, g_wqkv_r);
    cudaGetSymbolAddress((void**)&wp_r, g_wproj_r);

    cudaFuncSetAttribute(gemm_tf32,
                         cudaFuncAttributeMaxDynamicSharedMemorySize, GEMM_SMEM);
    cudaFuncSetAttribute(win_attn_mma,
                         cudaFuncAttributeMaxDynamicSharedMemorySize, ATTN_SMEM);

    // Pre-passes: rna-round x and weights to the tf32 grid
    const int nwq4 = 3 * CDIM * CDIM / 4, nwp4 = CDIM * CDIM / 4;
    round_tf32_vec<<<(nwq4 + 255) / 256, 256>>>(w_qkv, wq_r, nwq4);
    round_tf32_vec<<<(nwp4 + 255) / 256, 256>>>(w_proj, wp_r, nwp4);
    const int n4 = ROWS * CDIM / 4;
    round_tf32_vec<<<(n4 + 255) / 256, 256>>>(x, xr, n4);

    // 1) QKV projection (tensor cores, mma.sync tf32)
    gemm_tf32<<<dim3(3 * CDIM / 128, ROWS / 128), 256, GEMM_SMEM>>>(
        xr, wq_r, b_qkv, qkv, CDIM, 3 * CDIM);

    // 2) Windowed attention (mma.sync tf32, K/V hi-lo split)
    win_attn_mma<<<dim3(NWIN, NHEAD, BATCH), 256, ATTN_SMEM>>>(qkv, attn);

    // 3) Output projection (tensor cores, mma.sync tf32)
    gemm_tf32<<<dim3(CDIM / 128, ROWS / 128), 256, GEMM_SMEM>>>(
        attn, wp_r, b_proj, out, CDIM, CDIM);
}

// round 16
// speedup vs baseline: 3.5153x; 1.0169x over previous
#include <cuda_runtime.h>
#include <cstdint>

// ---------------------------------------------------------------------------
// HierarchicalAttention on GB300 (sm_103a)
// Round 16: attention V kept in natural [token][d] layout (conflict-free
// float4 stores); transpose moved to PV fragment reads (2-way max conflicts).
// GEMM = round-15 measured config (frozen). Numerics bit-identical.
// B=4, N=8192, C=1024, H=16, D=64, W=64
// ---------------------------------------------------------------------------

namespace {
constexpr int BATCH = 4;
constexpr int SEQ   = 8192;
constexpr int CDIM  = 1024;
constexpr int NHEAD = 16;
constexpr int HDIM  = 64;
constexpr int WIN   = 64;
constexpr int NWIN  = SEQ / WIN;          // 128
constexpr int ROWS  = BATCH * SEQ;        // 32768

constexpr int TILE_BYTES  = 128 * 32 * 4;             // 16 KB
constexpr int STAGE_BYTES = 2 * TILE_BYTES;           // A + B = 32 KB
constexpr int NSTAGE      = 3;
constexpr int GEMM_SMEM   = NSTAGE * STAGE_BYTES;     // 98,304 B -> 2 CTAs/SM

constexpr int APITCH    = 68;                         // attn smem pitch (4 mod 32)
constexpr int AMAT      = WIN * APITCH;               // floats per 64x68 array
constexpr int ATTN_SMEM = 6 * AMAT * 4;               // Q,Khi,Klo,Vhi,Vlo,P = 104,448 B
}

// Scratch (__device__ globals per allocation rules)
__device__ float g_x    [(size_t)ROWS * CDIM];          // rna-tf32-rounded x
__device__ float g_qkv  [(size_t)ROWS * 3 * CDIM];
__device__ float g_attn [(size_t)ROWS * CDIM];          // attn out (tf32-rounded)
__device__ float g_wqkv_r [(size_t)3 * CDIM * CDIM];    // rna-tf32-rounded weights
__device__ float g_wproj_r[(size_t)CDIM * CDIM];

// ---------------------------------------------------------------------------
// Helpers
// ---------------------------------------------------------------------------
#define SWZ128(x) ((x) ^ (((x) >> 3) & 0x70))

__device__ __forceinline__ void cp_async16(void* dst, const void* src) {
    uint32_t d;
    asm("{ .reg .u64 t; cvta.to.shared.u64 t, %1; cvt.u32.u64 %0, t; }"
        : "=r"(d) : "l"(dst));
    asm volatile("cp.async.cg.shared.global [%0], [%1], 16;" :: "r"(d), "l"(src));
}

__device__ __forceinline__ float rn_tf32(float v) {
    uint32_t u;
    asm("cvt.rna.tf32.f32 %0, %1;" : "=r"(u) : "f"(v));
    return __uint_as_float(u);
}

// mma.sync m16n8k8 tf32: D += A * B   (A row-major 16x8, B col-major 8x8)
__device__ __forceinline__ void mma_tf32(float* c, const uint32_t* a, const uint32_t* b) {
    asm volatile(
        "mma.sync.aligned.m16n8k8.row.col.f32.tf32.tf32.f32 "
        "{%0,%1,%2,%3}, {%4,%5,%6,%7}, {%8,%9}, {%0,%1,%2,%3};"
        : "+f"(c[0]), "+f"(c[1]), "+f"(c[2]), "+f"(c[3])
        : "r"(a[0]), "r"(a[1]), "r"(a[2]), "r"(a[3]), "r"(b[0]), "r"(b[1]));
}

__device__ __forceinline__ void mma_tf32_f(float* c, const float* a, const float* b) {
    mma_tf32(c, (const uint32_t*)a, (const uint32_t*)b);
}

// ---------------------------------------------------------------------------
// Conversion kernels (rna-round to tf32 grid)
// ---------------------------------------------------------------------------
__global__ void round_tf32_vec(const float* __restrict__ in, float* __restrict__ outp, int n4) {
    int i = blockIdx.x * blockDim.x + threadIdx.x;
    if (i < n4) {
        float4 v = ((const float4*)in)[i];
        v.x = rn_tf32(v.x); v.y = rn_tf32(v.y);
        v.z = rn_tf32(v.z); v.w = rn_tf32(v.w);
        ((float4*)outp)[i] = v;
    }
}

// ---------------------------------------------------------------------------
// tf32 GEMM (mma.sync): unchanged from round 15 (measured: 64.9% tensor).
// ---------------------------------------------------------------------------
__device__ __forceinline__ void load_tile_part(char* sbase, const float* __restrict__ g,
                                               int ld, int row0, int kk, int tid) {
#pragma unroll
    for (int i = 0; i < 4; i++) {
        const int e = tid + i * 256;
        const int r = e >> 3;
        const int c = e & 7;
        cp_async16(sbase + SWZ128(r * 128 + c * 16),
                   g + (size_t)(row0 + r) * ld + kk + c * 4);
    }
}

__global__ __launch_bounds__(256, 2)
void gemm_tf32(const float* __restrict__ A, const float* __restrict__ B,
               const float* __restrict__ bias, float* __restrict__ C,
               int K, int Ntot)
{
    extern __shared__ __align__(16) char smem[];
    const int tid  = threadIdx.x;
    const int wid  = tid >> 5;
    const int lane = tid & 31;
    const int m0 = blockIdx.y << 7;
    const int n0 = blockIdx.x << 7;
    const int nch = K >> 5;

    const int wm = (wid & 1) * 64;
    const int wn = (wid >> 1) * 32;
    const int rq = lane >> 2;
    const int cq = lane & 3;

    int swzA[4], swzB[4];
#pragma unroll
    for (int mt = 0; mt < 4; mt++)
        swzA[mt] = SWZ128((wm + mt * 16 + rq) * 128 + cq * 4);
#pragma unroll
    for (int nt = 0; nt < 4; nt++)
        swzB[nt] = SWZ128((wn + nt * 8 + rq) * 128 + cq * 4);

    float acc[4][4][4];
#pragma unroll
    for (int mt = 0; mt < 4; mt++)
#pragma unroll
        for (int nt = 0; nt < 4; nt++)
#pragma unroll
            for (int i = 0; i < 4; i++) acc[mt][nt][i] = 0.f;

    // Prologue: chunks 0..1 -> stages 0..1
#pragma unroll
    for (int j = 0; j < 2; j++) {
        char* st = smem + j * STAGE_BYTES;
        load_tile_part(st,              A, K, m0, j * 32, tid);
        load_tile_part(st + TILE_BYTES, B, K, n0, j * 32, tid);
        asm volatile("cp.async.commit_group;");
    }

    int cur = 0, nxt = 2;
    for (int k = 0; k < nch; k++) {
        asm volatile("cp.async.wait_group 1;");      // chunk k resident
        __syncthreads();

        // Refill FIRST: chunk k+2 flies while we compute chunk k.
        const int j = k + 2;
        if (j < nch) {
            char* ld = smem + nxt * STAGE_BYTES;
            load_tile_part(ld,              A, K, m0, j * 32, tid);
            load_tile_part(ld + TILE_BYTES, B, K, n0, j * 32, tid);
        }
        asm volatile("cp.async.commit_group;");      // (possibly empty) keep ledger

        const char* sA = smem + cur * STAGE_BYTES;
        const char* sB = sA + TILE_BYTES;

#pragma unroll
        for (int ks = 0; ks < 4; ks++) {
            const int ko = ks << 5;
            uint32_t af[4][4];
#pragma unroll
            for (int mt = 0; mt < 4; mt++) {
                const int a0 = swzA[mt] ^ ko;
                af[mt][0] = *(const uint32_t*)(sA + a0);
                af[mt][1] = *(const uint32_t*)(sA + a0 + 1024);
                af[mt][2] = *(const uint32_t*)(sA + (a0 ^ 16));
                af[mt][3] = *(const uint32_t*)(sA + ((a0 + 1024) ^ 16));
            }
#pragma unroll
            for (int nt = 0; nt < 4; nt++) {
                const int b0 = swzB[nt] ^ ko;
                uint32_t bf[2];
                bf[0] = *(const uint32_t*)(sB + b0);
                bf[1] = *(const uint32_t*)(sB + (b0 ^ 16));
#pragma unroll
                for (int mt = 0; mt < 4; mt++)
                    mma_tf32(acc[mt][nt], af[mt], bf);
            }
        }

        if (++cur == NSTAGE) cur = 0;
        if (++nxt == NSTAGE) nxt = 0;
    }

    // Epilogue: direct STG with bias (c0/c1 -> row, c2/c3 -> row+8)
#pragma unroll
    for (int nt = 0; nt < 4; nt++) {
        const int col = n0 + wn + nt * 8 + cq * 2;
        const float2 b2 = *(const float2*)&bias[col];
#pragma unroll
        for (int mt = 0; mt < 4; mt++) {
            const int row = m0 + wm + mt * 16 + rq;
            float2 v0, v1;
            v0.x = acc[mt][nt][0] + b2.x; v0.y = acc[mt][nt][1] + b2.y;
            v1.x = acc[mt][nt][2] + b2.x; v1.y = acc[mt][nt][3] + b2.y;
            *(float2*)&C[(size_t)row * Ntot + col]       = v0;
            *(float2*)&C[(size_t)(row + 8) * Ntot + col] = v1;
        }
    }
}

// ---------------------------------------------------------------------------
// Windowed attention via mma.sync tf32.
// Round 16 change: V stored NATURAL [token][d] (conflict-free float4 stores,
// same as K); the transpose happens at PV fragment-read time:
//   B[n=d][k=token] = Vhi[token*APITCH + d]  (max 2-way read conflicts).
// Operand values and MMA order identical to round 15 => bit-identical output.
// ---------------------------------------------------------------------------
__global__ __launch_bounds__(256)
void win_attn_mma(const float* __restrict__ qkv, float* __restrict__ out)
{
    extern __shared__ float sm[];
    float* Qs  = sm;               // [64][68], pre-scaled & rounded
    float* Khi = sm + AMAT;        // [token][d]
    float* Klo = sm + 2 * AMAT;
    float* Vhi = sm + 3 * AMAT;    // [token][d]  (natural layout now)
    float* Vlo = sm + 4 * AMAT;
    float* Ps  = sm + 5 * AMAT;    // [query][token]

    const int tid  = threadIdx.x;
    const int wid  = tid >> 5;
    const int lane = tid & 31;
    const int w = blockIdx.x, h = blockIdx.y, b = blockIdx.z;
    const int n0 = w * WIN;
    const size_t base = ((size_t)b * SEQ + n0) * (3 * CDIM) + (size_t)h * HDIM;

    // ---- Load Q (scaled+rounded), K hi/lo, V hi/lo (all natural layout) ----
#pragma unroll
    for (int i = 0; i < 4; i++) {
        const int e   = tid + i * 256;
        const int row = e >> 4;                 // token 0..63
        const int dc  = (e & 15) * 4;           // d offset
        const float* src = qkv + base + (size_t)row * (3 * CDIM) + dc;
        const float4 q4 = *(const float4*)(src);
        const float4 k4 = *(const float4*)(src + CDIM);
        const float4 v4 = *(const float4*)(src + 2 * CDIM);
        const int o = row * APITCH + dc;

        float4 qr;
        qr.x = rn_tf32(q4.x * 0.125f); qr.y = rn_tf32(q4.y * 0.125f);
        qr.z = rn_tf32(q4.z * 0.125f); qr.w = rn_tf32(q4.w * 0.125f);
        *(float4*)&Qs[o] = qr;

        float4 kh, kl;
        kh.x = rn_tf32(k4.x); kl.x = rn_tf32(k4.x - kh.x);
        kh.y = rn_tf32(k4.y); kl.y = rn_tf32(k4.y - kh.y);
        kh.z = rn_tf32(k4.z); kl.z = rn_tf32(k4.z - kh.z);
        kh.w = rn_tf32(k4.w); kl.w = rn_tf32(k4.w - kh.w);
        *(float4*)&Khi[o] = kh;
        *(float4*)&Klo[o] = kl;

        float4 vh, vl;
        vh.x = rn_tf32(v4.x); vl.x = rn_tf32(v4.x - vh.x);
        vh.y = rn_tf32(v4.y); vl.y = rn_tf32(v4.y - vh.y);
        vh.z = rn_tf32(v4.z); vl.z = rn_tf32(v4.z - vh.z);
        vh.w = rn_tf32(v4.w); vl.w = rn_tf32(v4.w - vh.w);
        *(float4*)&Vhi[o] = vh;
        *(float4*)&Vlo[o] = vl;
    }
    __syncthreads();

    const int m0w = (wid & 3) * 16;             // warp query-row base
    const int nh  = (wid >> 2) * 32;            // warp col base
    const int rq  = lane >> 2;
    const int cq  = lane & 3;

    // ---- S = Q K^T (K split: exact B side) ----
    {
        float sacc[4][4];
#pragma unroll
        for (int nt = 0; nt < 4; nt++)
#pragma unroll
            for (int i = 0; i < 4; i++) sacc[nt][i] = 0.f;

#pragma unroll
        for (int ks = 0; ks < 8; ks++) {
            const int ko = ks * 8;
            float af[4];
            af[0] = Qs[(m0w + rq)     * APITCH + ko + cq];
            af[1] = Qs[(m0w + rq + 8) * APITCH + ko + cq];
            af[2] = Qs[(m0w + rq)     * APITCH + ko + cq + 4];
            af[3] = Qs[(m0w + rq + 8) * APITCH + ko + cq + 4];
#pragma unroll
            for (int nt = 0; nt < 4; nt++) {
                const int nrow = (nh + nt * 8 + rq) * APITCH + ko + cq;
                float bh[2], bl[2];
                bh[0] = Khi[nrow]; bh[1] = Khi[nrow + 4];
                bl[0] = Klo[nrow]; bl[1] = Klo[nrow + 4];
                mma_tf32_f(sacc[nt], af, bh);
                mma_tf32_f(sacc[nt], af, bl);
            }
        }
#pragma unroll
        for (int nt = 0; nt < 4; nt++) {
            const int col = nh + nt * 8 + cq * 2;
            *(float2*)&Ps[(m0w + rq)     * APITCH + col] = make_float2(sacc[nt][0], sacc[nt][1]);
            *(float2*)&Ps[(m0w + rq + 8) * APITCH + col] = make_float2(sacc[nt][2], sacc[nt][3]);
        }
    }
    __syncthreads();

    // ---- softmax over rows of Ps; 1/sum folded, result tf32-rounded ----
    {
        const int row = tid >> 2;
        const int seg = tid & 3;
        float* pr = Ps + row * APITCH + seg * 16;
        float v[16];
#pragma unroll
        for (int i = 0; i < 4; i++) {
            const float4 t = *(const float4*)&pr[i * 4];
            v[i*4+0] = t.x; v[i*4+1] = t.y; v[i*4+2] = t.z; v[i*4+3] = t.w;
        }
        float mx = v[0];
#pragma unroll
        for (int i = 1; i < 16; i++) mx = fmaxf(mx, v[i]);
        mx = fmaxf(mx, __shfl_xor_sync(0xffffffffu, mx, 1));
        mx = fmaxf(mx, __shfl_xor_sync(0xffffffffu, mx, 2));
        float sum = 0.f;
#pragma unroll
        for (int i = 0; i < 16; i++) { v[i] = __expf(v[i] - mx); sum += v[i]; }
        sum += __shfl_xor_sync(0xffffffffu, sum, 1);
        sum += __shfl_xor_sync(0xffffffffu, sum, 2);
        const float inv = 1.f / sum;
#pragma unroll
        for (int i = 0; i < 4; i++) {
            float4 t;
            t.x = rn_tf32(v[i*4+0] * inv); t.y = rn_tf32(v[i*4+1] * inv);
            t.z = rn_tf32(v[i*4+2] * inv); t.w = rn_tf32(v[i*4+3] * inv);
            *(float4*)&pr[i * 4] = t;
        }
    }
    __syncthreads();

    // ---- O = P V (V split: exact B side, transpose at read) ----
    {
        float oacc[4][4];
#pragma unroll
        for (int nt = 0; nt < 4; nt++)
#pragma unroll
            for (int i = 0; i < 4; i++) oacc[nt][i] = 0.f;

#pragma unroll
        for (int ks = 0; ks < 8; ks++) {
            const int ko = ks * 8;
            float af[4];
            af[0] = Ps[(m0w + rq)     * APITCH + ko + cq];
            af[1] = Ps[(m0w + rq + 8) * APITCH + ko + cq];
            af[2] = Ps[(m0w + rq)     * APITCH + ko + cq + 4];
            af[3] = Ps[(m0w + rq + 8) * APITCH + ko + cq + 4];
#pragma unroll
            for (int nt = 0; nt < 4; nt++) {
                const int d = nh + nt * 8 + rq;            // B n-index = headdim
                float bh[2], bl[2];
                bh[0] = Vhi[(ko + cq)     * APITCH + d];   // B[k=token][...] read-transposed
                bh[1] = Vhi[(ko + cq + 4) * APITCH + d];
                bl[0] = Vlo[(ko + cq)     * APITCH + d];
                bl[1] = Vlo[(ko + cq + 4) * APITCH + d];
                mma_tf32_f(oacc[nt], af, bh);
                mma_tf32_f(oacc[nt], af, bl);
            }
        }

        const size_t row0 = (size_t)b * SEQ + n0 + m0w + rq;
#pragma unroll
        for (int nt = 0; nt < 4; nt++) {
            const int col = h * HDIM + nh + nt * 8 + cq * 2;
            float2 v0, v1;
            v0.x = rn_tf32(oacc[nt][0]); v0.y = rn_tf32(oacc[nt][1]);
            v1.x = rn_tf32(oacc[nt][2]); v1.y = rn_tf32(oacc[nt][3]);
            *(float2*)&out[row0 * CDIM + col]       = v0;
            *(float2*)&out[(row0 + 8) * CDIM + col] = v1;
        }
    }
}

// ---------------------------------------------------------------------------
// kernel_launch
// ---------------------------------------------------------------------------
extern "C" void kernel_launch(void* const* d_in, const int* in_sizes, int n_in,
                              void* d_out, int out_size)
{
    const float* x      = (const float*)d_in[0];
    const float* w_qkv  = (const float*)d_in[1];
    const float* b_qkv  = (const float*)d_in[2];
    const float* w_proj = (const float*)d_in[3];
    const float* b_proj = (const float*)d_in[4];
    float* out = (float*)d_out;

    float *xr, *qkv, *attn, *wq_r, *wp_r;
    cudaGetSymbolAddress((void**)&xr,   g_x);
    cudaGetSymbolAddress((void**)&qkv,  g_qkv);
    cudaGetSymbolAddress((void**)&attn, g_attn);
    cudaGetSymbolAddress((void**)&wq_r, g_wqkv_r);
    cudaGetSymbolAddress((void**)&wp_r, g_wproj_r);

    cudaFuncSetAttribute(gemm_tf32,
                         cudaFuncAttributeMaxDynamicSharedMemorySize, GEMM_SMEM);
    cudaFuncSetAttribute(win_attn_mma,
                         cudaFuncAttributeMaxDynamicSharedMemorySize, ATTN_SMEM);

    // Pre-passes: rna-round x and weights to the tf32 grid
    const int nwq4 = 3 * CDIM * CDIM / 4, nwp4 = CDIM * CDIM / 4;
    round_tf32_vec<<<(nwq4 + 255) / 256, 256>>>(w_qkv, wq_r, nwq4);
    round_tf32_vec<<<(nwp4 + 255) / 256, 256>>>(w_proj, wp_r, nwp4);
    const int n4 = ROWS * CDIM / 4;
    round_tf32_vec<<<(n4 + 255) / 256, 256>>>(x, xr, n4);

    // 1) QKV projection (tensor cores, mma.sync tf32)
    gemm_tf32<<<dim3(3 * CDIM / 128, ROWS / 128), 256, GEMM_SMEM>>>(
        xr, wq_r, b_qkv, qkv, CDIM, 3 * CDIM);

    // 2) Windowed attention (mma.sync tf32, K/V hi-lo split)
    win_attn_mma<<<dim3(NWIN, NHEAD, BATCH), 256, ATTN_SMEM>>>(qkv, attn);

    // 3) Output projection (tensor cores, mma.sync tf32)
    gemm_tf32<<<dim3(CDIM / 128, ROWS / 128), 256, GEMM_SMEM>>>(
        attn, wp_r, b_proj, out, CDIM, CDIM);
}

// round 17
// speedup vs baseline: 3.6349x; 1.0340x over previous
#include <cuda_runtime.h>
#include <cstdint>

// ---------------------------------------------------------------------------
// HierarchicalAttention on GB300 (sm_103a)
// Round 17: attention single-pass tf32 (K/V hi-lo split dropped; calibrated
// error model predicts ~7.6e-4 < 1e-3). Smem 104KB->70KB => 2 CTAs/SM.
// GEMM = round-15 measured config (frozen).
// B=4, N=8192, C=1024, H=16, D=64, W=64
// ---------------------------------------------------------------------------

namespace {
constexpr int BATCH = 4;
constexpr int SEQ   = 8192;
constexpr int CDIM  = 1024;
constexpr int NHEAD = 16;
constexpr int HDIM  = 64;
constexpr int WIN   = 64;
constexpr int NWIN  = SEQ / WIN;          // 128
constexpr int ROWS  = BATCH * SEQ;        // 32768

constexpr int TILE_BYTES  = 128 * 32 * 4;             // 16 KB
constexpr int STAGE_BYTES = 2 * TILE_BYTES;           // A + B = 32 KB
constexpr int NSTAGE      = 3;
constexpr int GEMM_SMEM   = NSTAGE * STAGE_BYTES;     // 98,304 B -> 2 CTAs/SM

constexpr int APITCH    = 68;                         // attn smem pitch (4 mod 32)
constexpr int AMAT      = WIN * APITCH;               // floats per 64x68 array
constexpr int ATTN_SMEM = 4 * AMAT * 4;               // Q,K,V,P = 69,632 B -> 2 CTAs/SM
}

// Scratch (__device__ globals per allocation rules)
__device__ float g_x    [(size_t)ROWS * CDIM];          // rna-tf32-rounded x
__device__ float g_qkv  [(size_t)ROWS * 3 * CDIM];
__device__ float g_attn [(size_t)ROWS * CDIM];          // attn out (tf32-rounded)
__device__ float g_wqkv_r [(size_t)3 * CDIM * CDIM];    // rna-tf32-rounded weights
__device__ float g_wproj_r[(size_t)CDIM * CDIM];

// ---------------------------------------------------------------------------
// Helpers
// ---------------------------------------------------------------------------
#define SWZ128(x) ((x) ^ (((x) >> 3) & 0x70))

__device__ __forceinline__ void cp_async16(void* dst, const void* src) {
    uint32_t d;
    asm("{ .reg .u64 t; cvta.to.shared.u64 t, %1; cvt.u32.u64 %0, t; }"
        : "=r"(d) : "l"(dst));
    asm volatile("cp.async.cg.shared.global [%0], [%1], 16;" :: "r"(d), "l"(src));
}

__device__ __forceinline__ float rn_tf32(float v) {
    uint32_t u;
    asm("cvt.rna.tf32.f32 %0, %1;" : "=r"(u) : "f"(v));
    return __uint_as_float(u);
}

// mma.sync m16n8k8 tf32: D += A * B   (A row-major 16x8, B col-major 8x8)
__device__ __forceinline__ void mma_tf32(float* c, const uint32_t* a, const uint32_t* b) {
    asm volatile(
        "mma.sync.aligned.m16n8k8.row.col.f32.tf32.tf32.f32 "
        "{%0,%1,%2,%3}, {%4,%5,%6,%7}, {%8,%9}, {%0,%1,%2,%3};"
        : "+f"(c[0]), "+f"(c[1]), "+f"(c[2]), "+f"(c[3])
        : "r"(a[0]), "r"(a[1]), "r"(a[2]), "r"(a[3]), "r"(b[0]), "r"(b[1]));
}

__device__ __forceinline__ void mma_tf32_f(float* c, const float* a, const float* b) {
    mma_tf32(c, (const uint32_t*)a, (const uint32_t*)b);
}

// ---------------------------------------------------------------------------
// Conversion kernels (rna-round to tf32 grid)
// ---------------------------------------------------------------------------
__global__ void round_tf32_vec(const float* __restrict__ in, float* __restrict__ outp, int n4) {
    int i = blockIdx.x * blockDim.x + threadIdx.x;
    if (i < n4) {
        float4 v = ((const float4*)in)[i];
        v.x = rn_tf32(v.x); v.y = rn_tf32(v.y);
        v.z = rn_tf32(v.z); v.w = rn_tf32(v.w);
        ((float4*)outp)[i] = v;
    }
}

// ---------------------------------------------------------------------------
// tf32 GEMM (mma.sync): unchanged from round 15 (measured: 64.9% tensor).
// ---------------------------------------------------------------------------
__device__ __forceinline__ void load_tile_part(char* sbase, const float* __restrict__ g,
                                               int ld, int row0, int kk, int tid) {
#pragma unroll
    for (int i = 0; i < 4; i++) {
        const int e = tid + i * 256;
        const int r = e >> 3;
        const int c = e & 7;
        cp_async16(sbase + SWZ128(r * 128 + c * 16),
                   g + (size_t)(row0 + r) * ld + kk + c * 4);
    }
}

__global__ __launch_bounds__(256, 2)
void gemm_tf32(const float* __restrict__ A, const float* __restrict__ B,
               const float* __restrict__ bias, float* __restrict__ C,
               int K, int Ntot)
{
    extern __shared__ __align__(16) char smem[];
    const int tid  = threadIdx.x;
    const int wid  = tid >> 5;
    const int lane = tid & 31;
    const int m0 = blockIdx.y << 7;
    const int n0 = blockIdx.x << 7;
    const int nch = K >> 5;

    const int wm = (wid & 1) * 64;
    const int wn = (wid >> 1) * 32;
    const int rq = lane >> 2;
    const int cq = lane & 3;

    int swzA[4], swzB[4];
#pragma unroll
    for (int mt = 0; mt < 4; mt++)
        swzA[mt] = SWZ128((wm + mt * 16 + rq) * 128 + cq * 4);
#pragma unroll
    for (int nt = 0; nt < 4; nt++)
        swzB[nt] = SWZ128((wn + nt * 8 + rq) * 128 + cq * 4);

    float acc[4][4][4];
#pragma unroll
    for (int mt = 0; mt < 4; mt++)
#pragma unroll
        for (int nt = 0; nt < 4; nt++)
#pragma unroll
            for (int i = 0; i < 4; i++) acc[mt][nt][i] = 0.f;

    // Prologue: chunks 0..1 -> stages 0..1
#pragma unroll
    for (int j = 0; j < 2; j++) {
        char* st = smem + j * STAGE_BYTES;
        load_tile_part(st,              A, K, m0, j * 32, tid);
        load_tile_part(st + TILE_BYTES, B, K, n0, j * 32, tid);
        asm volatile("cp.async.commit_group;");
    }

    int cur = 0, nxt = 2;
    for (int k = 0; k < nch; k++) {
        asm volatile("cp.async.wait_group 1;");      // chunk k resident
        __syncthreads();

        // Refill FIRST: chunk k+2 flies while we compute chunk k.
        const int j = k + 2;
        if (j < nch) {
            char* ld = smem + nxt * STAGE_BYTES;
            load_tile_part(ld,              A, K, m0, j * 32, tid);
            load_tile_part(ld + TILE_BYTES, B, K, n0, j * 32, tid);
        }
        asm volatile("cp.async.commit_group;");      // (possibly empty) keep ledger

        const char* sA = smem + cur * STAGE_BYTES;
        const char* sB = sA + TILE_BYTES;

#pragma unroll
        for (int ks = 0; ks < 4; ks++) {
            const int ko = ks << 5;
            uint32_t af[4][4];
#pragma unroll
            for (int mt = 0; mt < 4; mt++) {
                const int a0 = swzA[mt] ^ ko;
                af[mt][0] = *(const uint32_t*)(sA + a0);
                af[mt][1] = *(const uint32_t*)(sA + a0 + 1024);
                af[mt][2] = *(const uint32_t*)(sA + (a0 ^ 16));
                af[mt][3] = *(const uint32_t*)(sA + ((a0 + 1024) ^ 16));
            }
#pragma unroll
            for (int nt = 0; nt < 4; nt++) {
                const int b0 = swzB[nt] ^ ko;
                uint32_t bf[2];
                bf[0] = *(const uint32_t*)(sB + b0);
                bf[1] = *(const uint32_t*)(sB + (b0 ^ 16));
#pragma unroll
                for (int mt = 0; mt < 4; mt++)
                    mma_tf32(acc[mt][nt], af[mt], bf);
            }
        }

        if (++cur == NSTAGE) cur = 0;
        if (++nxt == NSTAGE) nxt = 0;
    }

    // Epilogue: direct STG with bias (c0/c1 -> row, c2/c3 -> row+8)
#pragma unroll
    for (int nt = 0; nt < 4; nt++) {
        const int col = n0 + wn + nt * 8 + cq * 2;
        const float2 b2 = *(const float2*)&bias[col];
#pragma unroll
        for (int mt = 0; mt < 4; mt++) {
            const int row = m0 + wm + mt * 16 + rq;
            float2 v0, v1;
            v0.x = acc[mt][nt][0] + b2.x; v0.y = acc[mt][nt][1] + b2.y;
            v1.x = acc[mt][nt][2] + b2.x; v1.y = acc[mt][nt][3] + b2.y;
            *(float2*)&C[(size_t)row * Ntot + col]       = v0;
            *(float2*)&C[(size_t)(row + 8) * Ntot + col] = v1;
        }
    }
}

// ---------------------------------------------------------------------------
// Windowed attention via mma.sync tf32 — round 17: single-pass K and V
// (rna-rounded once), Q/P rounded as before. Smem: Q,K,V,P = 69,632 B
// => 2 CTAs/SM for cross-CTA load/compute overlap.
// V natural [token][d]; transpose at PV fragment-read (round-16 measured).
// ---------------------------------------------------------------------------
__global__ __launch_bounds__(256, 2)
void win_attn_mma(const float* __restrict__ qkv, float* __restrict__ out)
{
    extern __shared__ float sm[];
    float* Qs = sm;                // [64][68], pre-scaled & rounded
    float* Ks = sm + AMAT;         // [token][d], rounded
    float* Vs = sm + 2 * AMAT;     // [token][d], rounded
    float* Ps = sm + 3 * AMAT;     // [query][token]

    const int tid  = threadIdx.x;
    const int wid  = tid >> 5;
    const int lane = tid & 31;
    const int w = blockIdx.x, h = blockIdx.y, b = blockIdx.z;
    const int n0 = w * WIN;
    const size_t base = ((size_t)b * SEQ + n0) * (3 * CDIM) + (size_t)h * HDIM;

    // ---- Load Q (scaled+rounded), K, V (rounded, natural layout) ----
#pragma unroll
    for (int i = 0; i < 4; i++) {
        const int e   = tid + i * 256;
        const int row = e >> 4;                 // token 0..63
        const int dc  = (e & 15) * 4;           // d offset
        const float* src = qkv + base + (size_t)row * (3 * CDIM) + dc;
        const float4 q4 = *(const float4*)(src);
        const float4 k4 = *(const float4*)(src + CDIM);
        const float4 v4 = *(const float4*)(src + 2 * CDIM);
        const int o = row * APITCH + dc;

        float4 qr;
        qr.x = rn_tf32(q4.x * 0.125f); qr.y = rn_tf32(q4.y * 0.125f);
        qr.z = rn_tf32(q4.z * 0.125f); qr.w = rn_tf32(q4.w * 0.125f);
        *(float4*)&Qs[o] = qr;

        float4 kr;
        kr.x = rn_tf32(k4.x); kr.y = rn_tf32(k4.y);
        kr.z = rn_tf32(k4.z); kr.w = rn_tf32(k4.w);
        *(float4*)&Ks[o] = kr;

        float4 vr;
        vr.x = rn_tf32(v4.x); vr.y = rn_tf32(v4.y);
        vr.z = rn_tf32(v4.z); vr.w = rn_tf32(v4.w);
        *(float4*)&Vs[o] = vr;
    }
    __syncthreads();

    const int m0w = (wid & 3) * 16;             // warp query-row base
    const int nh  = (wid >> 2) * 32;            // warp col base
    const int rq  = lane >> 2;
    const int cq  = lane & 3;

    // ---- S = Q K^T ----
    {
        float sacc[4][4];
#pragma unroll
        for (int nt = 0; nt < 4; nt++)
#pragma unroll
            for (int i = 0; i < 4; i++) sacc[nt][i] = 0.f;

#pragma unroll
        for (int ks = 0; ks < 8; ks++) {
            const int ko = ks * 8;
            float af[4];
            af[0] = Qs[(m0w + rq)     * APITCH + ko + cq];
            af[1] = Qs[(m0w + rq + 8) * APITCH + ko + cq];
            af[2] = Qs[(m0w + rq)     * APITCH + ko + cq + 4];
            af[3] = Qs[(m0w + rq + 8) * APITCH + ko + cq + 4];
#pragma unroll
            for (int nt = 0; nt < 4; nt++) {
                const int nrow = (nh + nt * 8 + rq) * APITCH + ko + cq;
                float bf[2];
                bf[0] = Ks[nrow]; bf[1] = Ks[nrow + 4];
                mma_tf32_f(sacc[nt], af, bf);
            }
        }
#pragma unroll
        for (int nt = 0; nt < 4; nt++) {
            const int col = nh + nt * 8 + cq * 2;
            *(float2*)&Ps[(m0w + rq)     * APITCH + col] = make_float2(sacc[nt][0], sacc[nt][1]);
            *(float2*)&Ps[(m0w + rq + 8) * APITCH + col] = make_float2(sacc[nt][2], sacc[nt][3]);
        }
    }
    __syncthreads();

    // ---- softmax over rows of Ps; 1/sum folded, result tf32-rounded ----
    {
        const int row = tid >> 2;
        const int seg = tid & 3;
        float* pr = Ps + row * APITCH + seg * 16;
        float v[16];
#pragma unroll
        for (int i = 0; i < 4; i++) {
            const float4 t = *(const float4*)&pr[i * 4];
            v[i*4+0] = t.x; v[i*4+1] = t.y; v[i*4+2] = t.z; v[i*4+3] = t.w;
        }
        float mx = v[0];
#pragma unroll
        for (int i = 1; i < 16; i++) mx = fmaxf(mx, v[i]);
        mx = fmaxf(mx, __shfl_xor_sync(0xffffffffu, mx, 1));
        mx = fmaxf(mx, __shfl_xor_sync(0xffffffffu, mx, 2));
        float sum = 0.f;
#pragma unroll
        for (int i = 0; i < 16; i++) { v[i] = __expf(v[i] - mx); sum += v[i]; }
        sum += __shfl_xor_sync(0xffffffffu, sum, 1);
        sum += __shfl_xor_sync(0xffffffffu, sum, 2);
        const float inv = 1.f / sum;
#pragma unroll
        for (int i = 0; i < 4; i++) {
            float4 t;
            t.x = rn_tf32(v[i*4+0] * inv); t.y = rn_tf32(v[i*4+1] * inv);
            t.z = rn_tf32(v[i*4+2] * inv); t.w = rn_tf32(v[i*4+3] * inv);
            *(float4*)&pr[i * 4] = t;
        }
    }
    __syncthreads();

    // ---- O = P V (transpose at read) ----
    {
        float oacc[4][4];
#pragma unroll
        for (int nt = 0; nt < 4; nt++)
#pragma unroll
            for (int i = 0; i < 4; i++) oacc[nt][i] = 0.f;

#pragma unroll
        for (int ks = 0; ks < 8; ks++) {
            const int ko = ks * 8;
            float af[4];
            af[0] = Ps[(m0w + rq)     * APITCH + ko + cq];
            af[1] = Ps[(m0w + rq + 8) * APITCH + ko + cq];
            af[2] = Ps[(m0w + rq)     * APITCH + ko + cq + 4];
            af[3] = Ps[(m0w + rq + 8) * APITCH + ko + cq + 4];
#pragma unroll
            for (int nt = 0; nt < 4; nt++) {
                const int d = nh + nt * 8 + rq;            // B n-index = headdim
                float bf[2];
                bf[0] = Vs[(ko + cq)     * APITCH + d];    // read-transposed
                bf[1] = Vs[(ko + cq + 4) * APITCH + d];
                mma_tf32_f(oacc[nt], af, bf);
            }
        }

        const size_t row0 = (size_t)b * SEQ + n0 + m0w + rq;
#pragma unroll
        for (int nt = 0; nt < 4; nt++) {
            const int col = h * HDIM + nh + nt * 8 + cq * 2;
            float2 v0, v1;
            v0.x = rn_tf32(oacc[nt][0]); v0.y = rn_tf32(oacc[nt][1]);
            v1.x = rn_tf32(oacc[nt][2]); v1.y = rn_tf32(oacc[nt][3]);
            *(float2*)&out[row0 * CDIM + col]       = v0;
            *(float2*)&out[(row0 + 8) * CDIM + col] = v1;
        }
    }
}

// ---------------------------------------------------------------------------
// kernel_launch
// ---------------------------------------------------------------------------
extern "C" void kernel_launch(void* const* d_in, const int* in_sizes, int n_in,
                              void* d_out, int out_size)
{
    const float* x      = (const float*)d_in[0];
    const float* w_qkv  = (const float*)d_in[1];
    const float* b_qkv  = (const float*)d_in[2];
    const float* w_proj = (const float*)d_in[3];
    const float* b_proj = (const float*)d_in[4];
    float* out = (float*)d_out;

    float *xr, *qkv, *attn, *wq_r, *wp_r;
    cudaGetSymbolAddress((void**)&xr,   g_x);
    cudaGetSymbolAddress((void**)&qkv,  g_qkv);
    cudaGetSymbolAddress((void**)&attn, g_attn);
    cudaGetSymbolAddress((void**)&wq_r, g_wqkv_r);
    cudaGetSymbolAddress((void**)&wp_r, g_wproj_r);

    cudaFuncSetAttribute(gemm_tf32,
                         cudaFuncAttributeMaxDynamicSharedMemorySize, GEMM_SMEM);
    cudaFuncSetAttribute(win_attn_mma,
                         cudaFuncAttributeMaxDynamicSharedMemorySize, ATTN_SMEM);

    // Pre-passes: rna-round x and weights to the tf32 grid
    const int nwq4 = 3 * CDIM * CDIM / 4, nwp4 = CDIM * CDIM / 4;
    round_tf32_vec<<<(nwq4 + 255) / 256, 256>>>(w_qkv, wq_r, nwq4);
    round_tf32_vec<<<(nwp4 + 255) / 256, 256>>>(w_proj, wp_r, nwp4);
    const int n4 = ROWS * CDIM / 4;
    round_tf32_vec<<<(n4 + 255) / 256, 256>>>(x, xr, n4);

    // 1) QKV projection (tensor cores, mma.sync tf32)
    gemm_tf32<<<dim3(3 * CDIM / 128, ROWS / 128), 256, GEMM_SMEM>>>(
        xr, wq_r, b_qkv, qkv, CDIM, 3 * CDIM);

    // 2) Windowed attention (mma.sync tf32, single-pass)
    win_attn_mma<<<dim3(NWIN, NHEAD, BATCH), 256, ATTN_SMEM>>>(qkv, attn);

    // 3) Output projection (tensor cores, mma.sync tf32)
    gemm_tf32<<<dim3(CDIM / 128, ROWS / 128), 256, GEMM_SMEM>>>(
        attn, wp_r, b_proj, out, CDIM, CDIM);
}